// round 1
// baseline (speedup 1.0000x reference)
#include <cuda_runtime.h>
#include <math.h>

#define NMAX  50176
#define GMAX  64
#define FDIM  128
#define HDIM  128
#define KDIM  32

// ---------------- scratch (static device globals; no allocation) -------------
__device__ float g_deg [NMAX];
__device__ float g_dinv[NMAX];
__device__ float g_y1  [NMAX * HDIM];   // y1 = dinv*(X@W1); overwritten in-place with h
__device__ float g_agg1[NMAX * HDIM];
__device__ float g_y2  [NMAX * KDIM];   // y2 = dinv*(h2@W2); overwritten in-place with Z
__device__ float g_agg2[NMAX * KDIM];
__device__ float g_msum1[GMAX * HDIM];
__device__ float g_r1  [GMAX * HDIM];
__device__ float g_msum2[GMAX * KDIM];
__device__ float g_r2  [GMAX * KDIM];
__device__ float g_cnt [GMAX];
__device__ int   g_is64_ei;
__device__ int   g_is64_batch;

__device__ __forceinline__ long long ld_idx(const void* p, long long pos, int is64) {
    if (is64) return ((const long long*)p)[pos];
    return (long long)((const int*)p)[pos];
}

// ---------------- dtype detection (int64 vs int32, decided from data) --------
__global__ void detect_kernel(const void* ei, const void* batch, long long E, int N) {
    if (threadIdx.x != 0 || blockIdx.x != 0) return;
    // edge index: sample 64 8-byte words spread over [0, E). If the data is
    // int64, every word is a node id < N. If int32, a word packs two ids and
    // is >= 2^32 unless the high id is exactly 0 (p ~ 2e-5 per sample).
    const unsigned long long* p = (const unsigned long long*)ei;
    int ok = 1;
    for (int i = 0; i < 64; i++) {
        long long w = (long long)i * (E - 1) / 63;
        if (p[w] >= (unsigned long long)N) { ok = 0; break; }
    }
    g_is64_ei = ok;
    // batch (sorted, values < 64): sample the LAST 64 words of the first N/2
    // 8-byte words (valid range under both interpretations). Near the end the
    // int32 values are ~63, so the packed-int64 interpretation is huge.
    const unsigned long long* q = (const unsigned long long*)batch;
    int ok2 = 1;
    for (int i = 0; i < 64; i++) {
        long long w = (long long)(N / 2) - 1 - i;
        if (w < 0) break;
        if (q[w] >= (unsigned long long)GMAX) { ok2 = 0; break; }
    }
    g_is64_batch = ok2;
}

// ---------------- init: zero accumulators, deg = 1 (self loop) ---------------
__global__ void init_kernel(int N) {
    int idx = blockIdx.x * blockDim.x + threadIdx.x;
    if (idx < N * HDIM) g_agg1[idx] = 0.f;
    if (idx < N * KDIM) g_agg2[idx] = 0.f;
    if (idx < N)        g_deg[idx]  = 1.f;
    if (idx < GMAX * HDIM) g_msum1[idx] = 0.f;
    if (idx < GMAX * KDIM) g_msum2[idx] = 0.f;
    if (idx < GMAX)        g_cnt[idx]   = 0.f;
}

__global__ void deg_kernel(const void* __restrict__ ei, long long E) {
    long long e = (long long)blockIdx.x * blockDim.x + threadIdx.x;
    if (e >= E) return;
    int is64 = g_is64_ei;
    int d = (int)ld_idx(ei, E + e, is64);
    atomicAdd(&g_deg[d], 1.f);
}

__global__ void dinv_kernel(int N) {
    int i = blockIdx.x * blockDim.x + threadIdx.x;
    if (i < N) g_dinv[i] = rsqrtf(g_deg[i]);   // deg >= 1 always
}

// ---------------- GEMM1: y1 = dinv .* (X @ W1)   [N,128]x[128,128] -----------
// Register-tiled SGEMM: block = 64 rows x 128 cols, 128 threads, 8x8 per thread.
__global__ void __launch_bounds__(128) gemm1_kernel(
    const float* __restrict__ X, const float* __restrict__ W, int N)
{
    __shared__ float As[16][64];    // A tile transposed: As[k][row]
    __shared__ float Bs[16][128];
    int t  = threadIdx.x;
    int tx = t & 15;      // col group: 8 cols
    int ty = t >> 4;      // row group: 8 rows
    int rowBase = blockIdx.x * 64;

    float acc[8][8];
#pragma unroll
    for (int i = 0; i < 8; i++)
#pragma unroll
        for (int j = 0; j < 8; j++) acc[i][j] = 0.f;

    for (int k0 = 0; k0 < 128; k0 += 16) {
        // load A tile 64x16 (transposed into smem)
#pragma unroll
        for (int u = 0; u < 2; u++) {
            int idx = t * 8 + u * 4;
            int r = idx >> 4, c = idx & 15;
            int grow = rowBase + r;
            float4 v = make_float4(0.f, 0.f, 0.f, 0.f);
            if (grow < N) v = *(const float4*)(X + (size_t)grow * 128 + k0 + c);
            As[c + 0][r] = v.x; As[c + 1][r] = v.y;
            As[c + 2][r] = v.z; As[c + 3][r] = v.w;
        }
        // load B tile 16x128
#pragma unroll
        for (int u = 0; u < 4; u++) {
            int idx = t * 16 + u * 4;
            int r = idx >> 7, c = idx & 127;
            *(float4*)&Bs[r][c] = *(const float4*)(W + (k0 + r) * 128 + c);
        }
        __syncthreads();
#pragma unroll
        for (int kk = 0; kk < 16; kk++) {
            float a[8], b[8];
            *(float4*)&a[0] = *(float4*)&As[kk][ty * 8];
            *(float4*)&a[4] = *(float4*)&As[kk][ty * 8 + 4];
            *(float4*)&b[0] = *(float4*)&Bs[kk][tx * 8];
            *(float4*)&b[4] = *(float4*)&Bs[kk][tx * 8 + 4];
#pragma unroll
            for (int i = 0; i < 8; i++)
#pragma unroll
                for (int j = 0; j < 8; j++)
                    acc[i][j] += a[i] * b[j];
        }
        __syncthreads();
    }
#pragma unroll
    for (int i = 0; i < 8; i++) {
        int grow = rowBase + ty * 8 + i;
        if (grow < N) {
            float dv = g_dinv[grow];
#pragma unroll
            for (int j = 0; j < 8; j += 4) {
                float4 v;
                v.x = acc[i][j + 0] * dv; v.y = acc[i][j + 1] * dv;
                v.z = acc[i][j + 2] * dv; v.w = acc[i][j + 3] * dv;
                *(float4*)(g_y1 + (size_t)grow * 128 + tx * 8 + j) = v;
            }
        }
    }
}

// ---------------- edge aggregation conv1: agg1[d] += y1[s]  (1 warp/edge) ----
__global__ void agg1_kernel(const void* __restrict__ ei, long long E) {
    long long gtid = (long long)blockIdx.x * blockDim.x + threadIdx.x;
    long long e = gtid >> 5;
    int lane = threadIdx.x & 31;
    if (e >= E) return;
    int is64 = g_is64_ei;
    int s = (int)ld_idx(ei, e, is64);
    int d = (int)ld_idx(ei, E + e, is64);
    float4 v = *(const float4*)(g_y1 + (size_t)s * 128 + lane * 4);
    float* dst = g_agg1 + (size_t)d * 128 + lane * 4;
    asm volatile("red.global.add.v4.f32 [%0], {%1, %2, %3, %4};"
                 :: "l"(dst), "f"(v.x), "f"(v.y), "f"(v.z), "f"(v.w) : "memory");
}

// ---- combine1: h = elu(dinv*(agg1+y1)+b1); pooled sums via run-length -------
__global__ void __launch_bounds__(128) combine1_kernel(
    const float* __restrict__ b1, const void* __restrict__ batch, int N)
{
    int j = threadIdx.x;                  // column 0..127
    int base = blockIdx.x * 64;
    int is64 = g_is64_batch;
    float bj = b1[j];
    float acc = 0.f; int curg = -1; int runcnt = 0;
    for (int r = 0; r < 64; r++) {
        int i = base + r;
        if (i >= N) break;
        float dv = g_dinv[i];
        size_t off = (size_t)i * 128 + j;
        float v = dv * (g_agg1[off] + g_y1[off]) + bj;
        float hv = v > 0.f ? v : expm1f(v);
        g_y1[off] = hv;                   // h stored in-place over y1
        int g = (int)ld_idx(batch, i, is64);
        if (g != curg) {
            if (curg >= 0) {
                atomicAdd(&g_msum1[curg * HDIM + j], acc);
                if (j == 0) atomicAdd(&g_cnt[curg], (float)runcnt);
            }
            acc = 0.f; runcnt = 0; curg = g;
        }
        acc += hv; runcnt++;
    }
    if (curg >= 0) {
        atomicAdd(&g_msum1[curg * HDIM + j], acc);
        if (j == 0) atomicAdd(&g_cnt[curg], (float)runcnt);
    }
}

// ---------------- master1: r1 = relu(mean_pool(h) @ mW1 + mb1)  [64,128] -----
__global__ void master1_kernel(const float* __restrict__ mW1,
                               const float* __restrict__ mb1) {
    __shared__ float m[HDIM];
    int g = blockIdx.x, j = threadIdx.x;
    float c = fmaxf(g_cnt[g], 1.f);
    m[j] = g_msum1[g * HDIM + j] / c;
    __syncthreads();
    float a = mb1[j];
#pragma unroll 4
    for (int k = 0; k < HDIM; k++) a += m[k] * mW1[k * HDIM + j];
    g_r1[g * HDIM + j] = fmaxf(a, 0.f);
}

// ---------------- GEMM2: y2 = dinv .* ((h + r1[batch]) @ W2)  [N,32] ---------
__global__ void __launch_bounds__(128) gemm2_kernel(
    const void* __restrict__ batch, const float* __restrict__ W2, int N)
{
    __shared__ float Ws[128 * 32];
    int t = threadIdx.x;
#pragma unroll
    for (int u = 0; u < 8; u++) {
        int idx = u * 512 + t * 4;
        *(float4*)&Ws[idx] = *(const float4*)&W2[idx];
    }
    __syncthreads();
    int i = blockIdx.x * 128 + t;
    if (i >= N) return;
    int g = (int)ld_idx(batch, i, g_is64_batch);
    const float* hr = g_y1 + (size_t)i * 128;
    const float* rr = g_r1 + g * 128;
    float4 acc[8];
#pragma unroll
    for (int j = 0; j < 8; j++) acc[j] = make_float4(0.f, 0.f, 0.f, 0.f);
#pragma unroll 2
    for (int k0 = 0; k0 < 128; k0 += 4) {
        float4 xv = *(const float4*)(hr + k0);
        float4 rv = *(const float4*)(rr + k0);
        float xs[4] = {xv.x + rv.x, xv.y + rv.y, xv.z + rv.z, xv.w + rv.w};
#pragma unroll
        for (int kk = 0; kk < 4; kk++) {
            const float4* wrow = (const float4*)&Ws[(k0 + kk) * 32];
            float x = xs[kk];
#pragma unroll
            for (int j = 0; j < 8; j++) {
                float4 w = wrow[j];
                acc[j].x += x * w.x; acc[j].y += x * w.y;
                acc[j].z += x * w.z; acc[j].w += x * w.w;
            }
        }
    }
    float dv = g_dinv[i];
#pragma unroll
    for (int j = 0; j < 8; j++) {
        float4 v = acc[j];
        v.x *= dv; v.y *= dv; v.z *= dv; v.w *= dv;
        *(float4*)(g_y2 + (size_t)i * 32 + j * 4) = v;
    }
}

// ---------------- edge aggregation conv2: agg2[d] += y2[s]  (8 lanes/edge) ---
__global__ void agg2_kernel(const void* __restrict__ ei, long long E) {
    long long gtid = (long long)blockIdx.x * blockDim.x + threadIdx.x;
    long long e = gtid >> 3;
    int sub = (int)(threadIdx.x & 7);
    if (e >= E) return;
    int is64 = g_is64_ei;
    int s = (int)ld_idx(ei, e, is64);
    int d = (int)ld_idx(ei, E + e, is64);
    float4 v = *(const float4*)(g_y2 + (size_t)s * 32 + sub * 4);
    float* dst = g_agg2 + (size_t)d * 32 + sub * 4;
    asm volatile("red.global.add.v4.f32 [%0], {%1, %2, %3, %4};"
                 :: "l"(dst), "f"(v.x), "f"(v.y), "f"(v.z), "f"(v.w) : "memory");
}

// ---------------- combine2: Z = dinv*(agg2+y2)+b2; pool sums -----------------
__global__ void combine2_kernel(const float* __restrict__ b2,
                                const void* __restrict__ batch, int N) {
    int idx = blockIdx.x * blockDim.x + threadIdx.x;
    if (idx >= N * KDIM) return;
    int i = idx >> 5, j = idx & 31;
    float dv = g_dinv[i];
    float z = dv * (g_agg2[idx] + g_y2[idx]) + b2[j];
    g_y2[idx] = z;                         // Z stored in-place over y2
    int g = (int)ld_idx(batch, i, g_is64_batch);
    atomicAdd(&g_msum2[g * KDIM + j], z);
}

// ---------------- master2: r2 = relu(mean_pool(Z) @ mW2 + mb2)  [64,32] ------
__global__ void master2_kernel(const float* __restrict__ mW2,
                               const float* __restrict__ mb2) {
    __shared__ float m[KDIM];
    int g = blockIdx.x, j = threadIdx.x;
    float c = fmaxf(g_cnt[g], 1.f);
    m[j] = g_msum2[g * KDIM + j] / c;
    __syncthreads();
    float a = mb2[j];
#pragma unroll
    for (int k = 0; k < KDIM; k++) a += m[k] * mW2[k * KDIM + j];
    g_r2[g * KDIM + j] = fmaxf(a, 0.f);
}

// ---------------- softmax over 32 cols (1 warp per row) ----------------------
__global__ void softmax_kernel(const void* __restrict__ batch,
                               float* __restrict__ out, int N) {
    int gtid = blockIdx.x * blockDim.x + threadIdx.x;
    int i = gtid >> 5;
    int j = threadIdx.x & 31;
    if (i >= N) return;
    int g = (int)ld_idx(batch, i, g_is64_batch);
    float z = g_y2[(size_t)i * 32 + j] + g_r2[g * 32 + j];
    float m = z;
#pragma unroll
    for (int o = 16; o > 0; o >>= 1) m = fmaxf(m, __shfl_xor_sync(0xffffffffu, m, o));
    float e = __expf(z - m);
    float s = e;
#pragma unroll
    for (int o = 16; o > 0; o >>= 1) s += __shfl_xor_sync(0xffffffffu, s, o);
    out[(size_t)i * 32 + j] = e / s;
}

// ---------------- launch ------------------------------------------------------
extern "C" void kernel_launch(void* const* d_in, const int* in_sizes, int n_in,
                              void* d_out, int out_size) {
    const float* X   = (const float*)d_in[0];
    const float* W1  = (const float*)d_in[1];
    const float* b1  = (const float*)d_in[2];
    const float* W2  = (const float*)d_in[3];
    const float* b2  = (const float*)d_in[4];
    const float* mW1 = (const float*)d_in[5];
    const float* mb1 = (const float*)d_in[6];
    const float* mW2 = (const float*)d_in[7];
    const float* mb2 = (const float*)d_in[8];
    const void*  ei  = d_in[9];
    const void*  bat = d_in[10];

    int N = in_sizes[0] / FDIM;
    long long E = in_sizes[9] / 2;
    float* out = (float*)d_out;

    detect_kernel<<<1, 32>>>(ei, bat, E, N);
    init_kernel<<<(N * HDIM + 255) / 256, 256>>>(N);
    deg_kernel<<<(int)((E + 255) / 256), 256>>>(ei, E);
    dinv_kernel<<<(N + 255) / 256, 256>>>(N);
    gemm1_kernel<<<(N + 63) / 64, 128>>>(X, W1, N);
    agg1_kernel<<<(int)((E * 32 + 255) / 256), 256>>>(ei, E);
    combine1_kernel<<<(N + 63) / 64, 128>>>(b1, bat, N);
    master1_kernel<<<GMAX, HDIM>>>(mW1, mb1);
    gemm2_kernel<<<(N + 127) / 128, 128>>>(bat, W2, N);
    agg2_kernel<<<(int)((E * 8 + 255) / 256), 256>>>(ei, E);
    combine2_kernel<<<(N * KDIM + 255) / 256, 256>>>(b2, bat, N);
    master2_kernel<<<GMAX, KDIM>>>(mW2, mb2);
    softmax_kernel<<<(N * 32 + 255) / 256, 256>>>(bat, out, N);
}

// round 2
// speedup vs baseline: 1.4277x; 1.4277x over previous
#include <cuda_runtime.h>
#include <math.h>

#define NMAX  50176
#define EMAX  1664000
#define GMAX  64
#define FDIM  128
#define HDIM  128
#define KDIM  32

// ---------------- scratch (static device globals; no allocation) -------------
__device__ float g_dinv[NMAX];
__device__ float g_y1  [NMAX * HDIM];   // y1 = dinv*(X@W1)
__device__ float g_h   [NMAX * HDIM];   // h after conv1 epilogue
__device__ float g_y2  [NMAX * KDIM];   // y2 = dinv*((h+r1)@W2)
__device__ float g_z   [NMAX * KDIM];   // Z after conv2 epilogue
__device__ float g_msum1[GMAX * HDIM];
__device__ float g_r1  [GMAX * HDIM];
__device__ float g_msum2[GMAX * KDIM];
__device__ float g_r2  [GMAX * KDIM];
__device__ float g_cnt [GMAX];
__device__ int   g_cnt_i[NMAX];        // in-degree (without self loop)
__device__ int   g_rowstart[NMAX];
__device__ int   g_cursor[NMAX];
__device__ int   g_bsums[64];
__device__ int   g_src32[EMAX];
__device__ int   g_dst32[EMAX];
__device__ int   g_csr  [EMAX];        // src ids sorted by dst
__device__ int   g_is64_ei;
__device__ int   g_is64_batch;

__device__ __forceinline__ long long ld_idx(const void* p, long long pos, int is64) {
    if (is64) return ((const long long*)p)[pos];
    return (long long)((const int*)p)[pos];
}

// ---------------- dtype detection (int64 vs int32, decided from data) --------
__global__ void detect_kernel(const void* ei, const void* batch, long long E, int N) {
    if (threadIdx.x != 0 || blockIdx.x != 0) return;
    const unsigned long long* p = (const unsigned long long*)ei;
    int ok = 1;
    for (int i = 0; i < 64; i++) {
        long long w = (long long)i * (E - 1) / 63;
        if (p[w] >= (unsigned long long)N) { ok = 0; break; }
    }
    g_is64_ei = ok;
    const unsigned long long* q = (const unsigned long long*)batch;
    int ok2 = 1;
    for (int i = 0; i < 64; i++) {
        long long w = (long long)(N / 2) - 1 - i;
        if (w < 0) break;
        if (q[w] >= (unsigned long long)GMAX) { ok2 = 0; break; }
    }
    g_is64_batch = ok2;
}

// ---------------- init: zero counters ----------------------------------------
__global__ void init_kernel(int N) {
    int idx = blockIdx.x * blockDim.x + threadIdx.x;
    if (idx < N)           g_cnt_i[idx] = 0;
    if (idx < GMAX * HDIM) g_msum1[idx] = 0.f;
    if (idx < GMAX * KDIM) g_msum2[idx] = 0.f;
    if (idx < GMAX)        g_cnt[idx]   = 0.f;
}

// ------------- histogram + convert indices to int32 --------------------------
__global__ void hist_kernel(const void* __restrict__ ei, long long E) {
    long long e = (long long)blockIdx.x * blockDim.x + threadIdx.x;
    if (e >= E) return;
    int is64 = g_is64_ei;
    int s = (int)ld_idx(ei, e, is64);
    int d = (int)ld_idx(ei, E + e, is64);
    g_src32[e] = s;
    g_dst32[e] = d;
    atomicAdd(&g_cnt_i[d], 1);
}

// ------------- prefix-sum over node counts (3 small kernels) ------------------
__global__ void scan1_kernel(int N) {
    __shared__ int sm[1024];
    int t = threadIdx.x;
    int idx = blockIdx.x * 1024 + t;
    int val = (idx < N) ? g_cnt_i[idx] : 0;
    sm[t] = val;
    __syncthreads();
    for (int off = 1; off < 1024; off <<= 1) {
        int x = (t >= off) ? sm[t - off] : 0;
        __syncthreads();
        sm[t] += x;
        __syncthreads();
    }
    if (idx < N) g_rowstart[idx] = sm[t] - val;   // exclusive, block-local
    if (t == 1023) g_bsums[blockIdx.x] = sm[1023];
}
__global__ void scan2_kernel(int nb) {
    if (threadIdx.x != 0) return;
    int run = 0;
    for (int b = 0; b < nb; b++) { int v = g_bsums[b]; g_bsums[b] = run; run += v; }
}
__global__ void scan3_kernel(int N) {
    int idx = blockIdx.x * blockDim.x + threadIdx.x;
    if (idx >= N) return;
    int v = g_rowstart[idx] + g_bsums[idx >> 10];
    g_rowstart[idx] = v;
    g_cursor[idx]   = v;
    g_dinv[idx]     = rsqrtf((float)g_cnt_i[idx] + 1.0f);   // +1 self loop
}

// ------------- scatter-fill CSR (src sorted by dst) ---------------------------
__global__ void fill_kernel(long long E) {
    long long e = (long long)blockIdx.x * blockDim.x + threadIdx.x;
    if (e >= E) return;
    int d = g_dst32[e];
    int pos = atomicAdd(&g_cursor[d], 1);
    g_csr[pos] = g_src32[e];
}

// ---------------- GEMM1: y1 = dinv .* (X @ W1)   [N,128]x[128,128] -----------
__global__ void __launch_bounds__(128) gemm1_kernel(
    const float* __restrict__ X, const float* __restrict__ W, int N)
{
    __shared__ float As[16][64];
    __shared__ float Bs[16][128];
    int t  = threadIdx.x;
    int tx = t & 15;
    int ty = t >> 4;
    int rowBase = blockIdx.x * 64;

    float acc[8][8];
#pragma unroll
    for (int i = 0; i < 8; i++)
#pragma unroll
        for (int j = 0; j < 8; j++) acc[i][j] = 0.f;

    for (int k0 = 0; k0 < 128; k0 += 16) {
#pragma unroll
        for (int u = 0; u < 2; u++) {
            int idx = t * 8 + u * 4;
            int r = idx >> 4, c = idx & 15;
            int grow = rowBase + r;
            float4 v = make_float4(0.f, 0.f, 0.f, 0.f);
            if (grow < N) v = *(const float4*)(X + (size_t)grow * 128 + k0 + c);
            As[c + 0][r] = v.x; As[c + 1][r] = v.y;
            As[c + 2][r] = v.z; As[c + 3][r] = v.w;
        }
#pragma unroll
        for (int u = 0; u < 4; u++) {
            int idx = t * 16 + u * 4;
            int r = idx >> 7, c = idx & 127;
            *(float4*)&Bs[r][c] = *(const float4*)(W + (k0 + r) * 128 + c);
        }
        __syncthreads();
#pragma unroll
        for (int kk = 0; kk < 16; kk++) {
            float a[8], b[8];
            *(float4*)&a[0] = *(float4*)&As[kk][ty * 8];
            *(float4*)&a[4] = *(float4*)&As[kk][ty * 8 + 4];
            *(float4*)&b[0] = *(float4*)&Bs[kk][tx * 8];
            *(float4*)&b[4] = *(float4*)&Bs[kk][tx * 8 + 4];
#pragma unroll
            for (int i = 0; i < 8; i++)
#pragma unroll
                for (int j = 0; j < 8; j++)
                    acc[i][j] += a[i] * b[j];
        }
        __syncthreads();
    }
#pragma unroll
    for (int i = 0; i < 8; i++) {
        int grow = rowBase + ty * 8 + i;
        if (grow < N) {
            float dv = g_dinv[grow];
#pragma unroll
            for (int j = 0; j < 8; j += 4) {
                float4 v;
                v.x = acc[i][j + 0] * dv; v.y = acc[i][j + 1] * dv;
                v.z = acc[i][j + 2] * dv; v.w = acc[i][j + 3] * dv;
                *(float4*)(g_y1 + (size_t)grow * 128 + tx * 8 + j) = v;
            }
        }
    }
}

// ----- agg1 (gather) + epilogue: h = elu(dinv*(self + sum_nbrs) + b1) --------
__global__ void __launch_bounds__(256) agg1_kernel(const float* __restrict__ b1, int N) {
    int warp = (blockIdx.x * blockDim.x + threadIdx.x) >> 5;
    int lane = threadIdx.x & 31;
    if (warp >= N) return;
    int i = warp;
    int beg  = g_rowstart[i];
    int cntE = g_cnt_i[i];
    const float4* base = (const float4*)g_y1;
    float4 acc = base[(size_t)i * 32 + lane];   // self loop
    int full = cntE & ~31;
    for (int k = 0; k < full; k += 32) {
        int myS = g_csr[beg + k + lane];
#pragma unroll 8
        for (int j = 0; j < 32; j++) {
            int s = __shfl_sync(0xffffffffu, myS, j);
            float4 v = base[(size_t)s * 32 + lane];
            acc.x += v.x; acc.y += v.y; acc.z += v.z; acc.w += v.w;
        }
    }
    int rem = cntE - full;
    if (rem) {
        int myS = (lane < rem) ? g_csr[beg + full + lane] : 0;
        for (int j = 0; j < rem; j++) {
            int s = __shfl_sync(0xffffffffu, myS, j);
            float4 v = base[(size_t)s * 32 + lane];
            acc.x += v.x; acc.y += v.y; acc.z += v.z; acc.w += v.w;
        }
    }
    float dv = g_dinv[i];
    float4 bb = ((const float4*)b1)[lane];
    float4 h;
    float vx = dv * acc.x + bb.x; h.x = vx > 0.f ? vx : expm1f(vx);
    float vy = dv * acc.y + bb.y; h.y = vy > 0.f ? vy : expm1f(vy);
    float vz = dv * acc.z + bb.z; h.z = vz > 0.f ? vz : expm1f(vz);
    float vw = dv * acc.w + bb.w; h.w = vw > 0.f ? vw : expm1f(vw);
    ((float4*)g_h)[(size_t)i * 32 + lane] = h;
}

// ------- pool1: run-length batched atomics into msum1 + graph counts ---------
__global__ void __launch_bounds__(128) pool1_kernel(const void* __restrict__ batch, int N) {
    int j = threadIdx.x;
    int base = blockIdx.x * 64;
    int is64 = g_is64_batch;
    float acc = 0.f; int curg = -1; int runcnt = 0;
    for (int r = 0; r < 64; r++) {
        int i = base + r;
        if (i >= N) break;
        float hv = g_h[(size_t)i * 128 + j];
        int g = (int)ld_idx(batch, i, is64);
        if (g != curg) {
            if (curg >= 0) {
                atomicAdd(&g_msum1[curg * HDIM + j], acc);
                if (j == 0) atomicAdd(&g_cnt[curg], (float)runcnt);
            }
            acc = 0.f; runcnt = 0; curg = g;
        }
        acc += hv; runcnt++;
    }
    if (curg >= 0) {
        atomicAdd(&g_msum1[curg * HDIM + j], acc);
        if (j == 0) atomicAdd(&g_cnt[curg], (float)runcnt);
    }
}

// ---------------- master1: r1 = relu(mean_pool(h) @ mW1 + mb1) ---------------
__global__ void master1_kernel(const float* __restrict__ mW1,
                               const float* __restrict__ mb1) {
    __shared__ float m[HDIM];
    int g = blockIdx.x, j = threadIdx.x;
    float c = fmaxf(g_cnt[g], 1.f);
    m[j] = g_msum1[g * HDIM + j] / c;
    __syncthreads();
    float a = mb1[j];
#pragma unroll 4
    for (int k = 0; k < HDIM; k++) a += m[k] * mW1[k * HDIM + j];
    g_r1[g * HDIM + j] = fmaxf(a, 0.f);
}

// ---------------- GEMM2: y2 = dinv .* ((h + r1[batch]) @ W2)  [N,32] ---------
__global__ void __launch_bounds__(128) gemm2_kernel(
    const void* __restrict__ batch, const float* __restrict__ W2, int N)
{
    __shared__ float Ws[128 * 32];
    int t = threadIdx.x;
#pragma unroll
    for (int u = 0; u < 8; u++) {
        int idx = u * 512 + t * 4;
        *(float4*)&Ws[idx] = *(const float4*)&W2[idx];
    }
    __syncthreads();
    int i = blockIdx.x * 128 + t;
    if (i >= N) return;
    int g = (int)ld_idx(batch, i, g_is64_batch);
    const float* hr = g_h + (size_t)i * 128;
    const float* rr = g_r1 + g * 128;
    float4 acc[8];
#pragma unroll
    for (int j = 0; j < 8; j++) acc[j] = make_float4(0.f, 0.f, 0.f, 0.f);
#pragma unroll 2
    for (int k0 = 0; k0 < 128; k0 += 4) {
        float4 xv = *(const float4*)(hr + k0);
        float4 rv = *(const float4*)(rr + k0);
        float xs[4] = {xv.x + rv.x, xv.y + rv.y, xv.z + rv.z, xv.w + rv.w};
#pragma unroll
        for (int kk = 0; kk < 4; kk++) {
            const float4* wrow = (const float4*)&Ws[(k0 + kk) * 32];
            float x = xs[kk];
#pragma unroll
            for (int j = 0; j < 8; j++) {
                float4 w = wrow[j];
                acc[j].x += x * w.x; acc[j].y += x * w.y;
                acc[j].z += x * w.z; acc[j].w += x * w.w;
            }
        }
    }
    float dv = g_dinv[i];
#pragma unroll
    for (int j = 0; j < 8; j++) {
        float4 v = acc[j];
        v.x *= dv; v.y *= dv; v.z *= dv; v.w *= dv;
        *(float4*)(g_y2 + (size_t)i * 32 + j * 4) = v;
    }
}

// ----- agg2 (gather) + epilogue: Z = dinv*(self + sum_nbrs) + b2 -------------
__global__ void __launch_bounds__(256) agg2_kernel(const float* __restrict__ b2, int N) {
    int warp = (blockIdx.x * blockDim.x + threadIdx.x) >> 5;
    int lane = threadIdx.x & 31;
    if (warp >= N) return;
    int i = warp;
    int beg  = g_rowstart[i];
    int cntE = g_cnt_i[i];
    float acc = g_y2[(size_t)i * 32 + lane];    // self loop
    int full = cntE & ~31;
    for (int k = 0; k < full; k += 32) {
        int myS = g_csr[beg + k + lane];
#pragma unroll 8
        for (int j = 0; j < 32; j++) {
            int s = __shfl_sync(0xffffffffu, myS, j);
            acc += g_y2[(size_t)s * 32 + lane];
        }
    }
    int rem = cntE - full;
    if (rem) {
        int myS = (lane < rem) ? g_csr[beg + full + lane] : 0;
        for (int j = 0; j < rem; j++) {
            int s = __shfl_sync(0xffffffffu, myS, j);
            acc += g_y2[(size_t)s * 32 + lane];
        }
    }
    g_z[(size_t)i * 32 + lane] = g_dinv[i] * acc + b2[lane];
}

// ------- pool2: run-length batched atomics into msum2 ------------------------
__global__ void __launch_bounds__(128) pool2_kernel(const void* __restrict__ batch, int N) {
    int j = threadIdx.x & 31;
    int seg = threadIdx.x >> 5;                // 4 warps per block
    int base = blockIdx.x * 256 + seg * 64;
    int is64 = g_is64_batch;
    float acc = 0.f; int curg = -1;
    for (int r = 0; r < 64; r++) {
        int i = base + r;
        if (i >= N) break;
        float zv = g_z[(size_t)i * 32 + j];
        int g = (int)ld_idx(batch, i, is64);
        if (g != curg) {
            if (curg >= 0) atomicAdd(&g_msum2[curg * KDIM + j], acc);
            acc = 0.f; curg = g;
        }
        acc += zv;
    }
    if (curg >= 0) atomicAdd(&g_msum2[curg * KDIM + j], acc);
}

// ---------------- master2: r2 = relu(mean_pool(Z) @ mW2 + mb2) ---------------
__global__ void master2_kernel(const float* __restrict__ mW2,
                               const float* __restrict__ mb2) {
    __shared__ float m[KDIM];
    int g = blockIdx.x, j = threadIdx.x;
    float c = fmaxf(g_cnt[g], 1.f);
    m[j] = g_msum2[g * KDIM + j] / c;
    __syncthreads();
    float a = mb2[j];
#pragma unroll
    for (int k = 0; k < KDIM; k++) a += m[k] * mW2[k * KDIM + j];
    g_r2[g * KDIM + j] = fmaxf(a, 0.f);
}

// ---------------- softmax over 32 cols (1 warp per row) ----------------------
__global__ void softmax_kernel(const void* __restrict__ batch,
                               float* __restrict__ out, int N) {
    int gtid = blockIdx.x * blockDim.x + threadIdx.x;
    int i = gtid >> 5;
    int j = threadIdx.x & 31;
    if (i >= N) return;
    int g = (int)ld_idx(batch, i, g_is64_batch);
    float z = g_z[(size_t)i * 32 + j] + g_r2[g * 32 + j];
    float m = z;
#pragma unroll
    for (int o = 16; o > 0; o >>= 1) m = fmaxf(m, __shfl_xor_sync(0xffffffffu, m, o));
    float e = __expf(z - m);
    float s = e;
#pragma unroll
    for (int o = 16; o > 0; o >>= 1) s += __shfl_xor_sync(0xffffffffu, s, o);
    out[(size_t)i * 32 + j] = e / s;
}

// ---------------- launch ------------------------------------------------------
extern "C" void kernel_launch(void* const* d_in, const int* in_sizes, int n_in,
                              void* d_out, int out_size) {
    const float* X   = (const float*)d_in[0];
    const float* W1  = (const float*)d_in[1];
    const float* b1  = (const float*)d_in[2];
    const float* W2  = (const float*)d_in[3];
    const float* b2  = (const float*)d_in[4];
    const float* mW1 = (const float*)d_in[5];
    const float* mb1 = (const float*)d_in[6];
    const float* mW2 = (const float*)d_in[7];
    const float* mb2 = (const float*)d_in[8];
    const void*  ei  = d_in[9];
    const void*  bat = d_in[10];

    int N = in_sizes[0] / FDIM;
    long long E = in_sizes[9] / 2;
    float* out = (float*)d_out;

    int nScanBlocks = (N + 1023) / 1024;

    detect_kernel<<<1, 32>>>(ei, bat, E, N);
    init_kernel<<<(GMAX * HDIM + 255) / 256 > (N + 255) / 256 ?
                  (GMAX * HDIM + 255) / 256 : (N + 255) / 256, 256>>>(N);
    hist_kernel<<<(int)((E + 255) / 256), 256>>>(ei, E);
    scan1_kernel<<<nScanBlocks, 1024>>>(N);
    scan2_kernel<<<1, 32>>>(nScanBlocks);
    scan3_kernel<<<(N + 255) / 256, 256>>>(N);
    fill_kernel<<<(int)((E + 255) / 256), 256>>>(E);
    gemm1_kernel<<<(N + 63) / 64, 128>>>(X, W1, N);
    agg1_kernel<<<(N * 32 + 255) / 256, 256>>>(b1, N);
    pool1_kernel<<<(N + 63) / 64, 128>>>(bat, N);
    master1_kernel<<<GMAX, HDIM>>>(mW1, mb1);
    gemm2_kernel<<<(N + 127) / 128, 128>>>(bat, W2, N);
    agg2_kernel<<<(N * 32 + 255) / 256, 256>>>(b2, N);
    pool2_kernel<<<(N + 255) / 256, 128>>>(bat, N);
    master2_kernel<<<GMAX, KDIM>>>(mW2, mb2);
    softmax_kernel<<<(N * 32 + 255) / 256, 256>>>(bat, out, N);
}

// round 3
// speedup vs baseline: 1.5179x; 1.0632x over previous
#include <cuda_runtime.h>
#include <math.h>

#define NMAX  50176
#define EMAX  1664000
#define GMAX  64
#define FDIM  128
#define HDIM  128
#define KDIM  32

// ---------------- scratch (static device globals; no allocation) -------------
__device__ float g_dinv[NMAX];
__device__ float g_y1  [NMAX * HDIM];   // xw = X@W1 (UNSCALED)
__device__ float g_h   [NMAX * HDIM];   // h after conv1 epilogue
__device__ float g_y2  [NMAX * KDIM];   // y2 = dinv*((h+r1)@W2)
__device__ float g_z   [NMAX * KDIM];   // Z after conv2 epilogue
__device__ float g_msum1[GMAX * HDIM];
__device__ float g_r1  [GMAX * HDIM];
__device__ float g_msum2[GMAX * KDIM];
__device__ float g_r2  [GMAX * KDIM];
__device__ float g_cnt [GMAX];
__device__ int   g_cnt_i[NMAX];        // in-degree (without self loop)
__device__ int   g_rowstart[NMAX];
__device__ int   g_cursor[NMAX];
__device__ int   g_bsums[64];
__device__ int   g_src32[EMAX];
__device__ int   g_dst32[EMAX];
__device__ int   g_csr  [EMAX];        // src ids sorted by dst
__device__ int   g_is64_ei;
__device__ int   g_is64_batch;

__device__ __forceinline__ long long ld_idx(const void* p, long long pos, int is64) {
    if (is64) return ((const long long*)p)[pos];
    return (long long)((const int*)p)[pos];
}

// ---------------- dtype detection (int64 vs int32, decided from data) --------
__global__ void detect_kernel(const void* ei, const void* batch, long long E, int N) {
    if (threadIdx.x != 0 || blockIdx.x != 0) return;
    const unsigned long long* p = (const unsigned long long*)ei;
    int ok = 1;
    for (int i = 0; i < 64; i++) {
        long long w = (long long)i * (E - 1) / 63;
        if (p[w] >= (unsigned long long)N) { ok = 0; break; }
    }
    g_is64_ei = ok;
    const unsigned long long* q = (const unsigned long long*)batch;
    int ok2 = 1;
    for (int i = 0; i < 64; i++) {
        long long w = (long long)(N / 2) - 1 - i;
        if (w < 0) break;
        if (q[w] >= (unsigned long long)GMAX) { ok2 = 0; break; }
    }
    g_is64_batch = ok2;
}

// ---------------- init: zero counters ----------------------------------------
__global__ void init_kernel(int N) {
    int idx = blockIdx.x * blockDim.x + threadIdx.x;
    if (idx < N)           g_cnt_i[idx] = 0;
    if (idx < GMAX * HDIM) g_msum1[idx] = 0.f;
    if (idx < GMAX * KDIM) g_msum2[idx] = 0.f;
    if (idx < GMAX)        g_cnt[idx]   = 0.f;
}

// ------------- histogram + convert indices to int32 --------------------------
__global__ void hist_kernel(const void* __restrict__ ei, long long E) {
    long long e = (long long)blockIdx.x * blockDim.x + threadIdx.x;
    if (e >= E) return;
    int is64 = g_is64_ei;
    int s = (int)ld_idx(ei, e, is64);
    int d = (int)ld_idx(ei, E + e, is64);
    g_src32[e] = s;
    g_dst32[e] = d;
    atomicAdd(&g_cnt_i[d], 1);
}

// ------------- prefix-sum over node counts (3 small kernels) ------------------
__global__ void scan1_kernel(int N) {
    __shared__ int sm[1024];
    int t = threadIdx.x;
    int idx = blockIdx.x * 1024 + t;
    int val = (idx < N) ? g_cnt_i[idx] : 0;
    sm[t] = val;
    __syncthreads();
    for (int off = 1; off < 1024; off <<= 1) {
        int x = (t >= off) ? sm[t - off] : 0;
        __syncthreads();
        sm[t] += x;
        __syncthreads();
    }
    if (idx < N) g_rowstart[idx] = sm[t] - val;   // exclusive, block-local
    if (t == 1023) g_bsums[blockIdx.x] = sm[1023];
}
__global__ void scan2_kernel(int nb) {
    if (threadIdx.x != 0) return;
    int run = 0;
    for (int b = 0; b < nb; b++) { int v = g_bsums[b]; g_bsums[b] = run; run += v; }
}
__global__ void scan3_kernel(int N) {
    int idx = blockIdx.x * blockDim.x + threadIdx.x;
    if (idx >= N) return;
    int v = g_rowstart[idx] + g_bsums[idx >> 10];
    g_rowstart[idx] = v;
    g_cursor[idx]   = v;
    g_dinv[idx]     = rsqrtf((float)g_cnt_i[idx] + 1.0f);   // +1 self loop
}

// ------------- scatter-fill CSR (src sorted by dst) ---------------------------
__global__ void fill_kernel(long long E) {
    long long e = (long long)blockIdx.x * blockDim.x + threadIdx.x;
    if (e >= E) return;
    int d = g_dst32[e];
    int pos = atomicAdd(&g_cursor[d], 1);
    g_csr[pos] = g_src32[e];
}

// ---------------- GEMM1: xw = X @ W1 (unscaled)  [N,128]x[128,128] -----------
__global__ void __launch_bounds__(128) gemm1_kernel(
    const float* __restrict__ X, const float* __restrict__ W, int N)
{
    __shared__ float As[16][64];
    __shared__ float Bs[16][128];
    int t  = threadIdx.x;
    int tx = t & 15;
    int ty = t >> 4;
    int rowBase = blockIdx.x * 64;

    float acc[8][8];
#pragma unroll
    for (int i = 0; i < 8; i++)
#pragma unroll
        for (int j = 0; j < 8; j++) acc[i][j] = 0.f;

    for (int k0 = 0; k0 < 128; k0 += 16) {
#pragma unroll
        for (int u = 0; u < 2; u++) {
            int idx = t * 8 + u * 4;
            int r = idx >> 4, c = idx & 15;
            int grow = rowBase + r;
            float4 v = make_float4(0.f, 0.f, 0.f, 0.f);
            if (grow < N) v = *(const float4*)(X + (size_t)grow * 128 + k0 + c);
            As[c + 0][r] = v.x; As[c + 1][r] = v.y;
            As[c + 2][r] = v.z; As[c + 3][r] = v.w;
        }
#pragma unroll
        for (int u = 0; u < 4; u++) {
            int idx = t * 16 + u * 4;
            int r = idx >> 7, c = idx & 127;
            *(float4*)&Bs[r][c] = *(const float4*)(W + (k0 + r) * 128 + c);
        }
        __syncthreads();
#pragma unroll
        for (int kk = 0; kk < 16; kk++) {
            float a[8], b[8];
            *(float4*)&a[0] = *(float4*)&As[kk][ty * 8];
            *(float4*)&a[4] = *(float4*)&As[kk][ty * 8 + 4];
            *(float4*)&b[0] = *(float4*)&Bs[kk][tx * 8];
            *(float4*)&b[4] = *(float4*)&Bs[kk][tx * 8 + 4];
#pragma unroll
            for (int i = 0; i < 8; i++)
#pragma unroll
                for (int j = 0; j < 8; j++)
                    acc[i][j] += a[i] * b[j];
        }
        __syncthreads();
    }
#pragma unroll
    for (int i = 0; i < 8; i++) {
        int grow = rowBase + ty * 8 + i;
        if (grow < N) {
#pragma unroll
            for (int j = 0; j < 8; j += 4) {
                float4 v;
                v.x = acc[i][j + 0]; v.y = acc[i][j + 1];
                v.z = acc[i][j + 2]; v.w = acc[i][j + 3];
                *(float4*)(g_y1 + (size_t)grow * 128 + tx * 8 + j) = v;
            }
        }
    }
}

// ----- agg1 (gather): h = elu(dinv[i]*(dinv[i]*xw[i] + sum dinv[s]*xw[s]) + b1)
__global__ void __launch_bounds__(256) agg1_kernel(const float* __restrict__ b1, int N) {
    int warp = (blockIdx.x * blockDim.x + threadIdx.x) >> 5;
    int lane = threadIdx.x & 31;
    if (warp >= N) return;
    int i = warp;
    int beg  = g_rowstart[i];
    int cntE = g_cnt_i[i];
    float dv = g_dinv[i];
    const float4* base = (const float4*)g_y1;
    float4 self = base[(size_t)i * 32 + lane];
    float4 acc;
    acc.x = dv * self.x; acc.y = dv * self.y;
    acc.z = dv * self.z; acc.w = dv * self.w;
    int full = cntE & ~31;
    for (int k = 0; k < full; k += 32) {
        int   myS = g_csr[beg + k + lane];
        float myD = g_dinv[myS];
#pragma unroll 8
        for (int j = 0; j < 32; j++) {
            int   s = __shfl_sync(0xffffffffu, myS, j);
            float w = __shfl_sync(0xffffffffu, myD, j);
            float4 v = base[(size_t)s * 32 + lane];
            acc.x += w * v.x; acc.y += w * v.y;
            acc.z += w * v.z; acc.w += w * v.w;
        }
    }
    int rem = cntE - full;
    if (rem) {
        int   myS = (lane < rem) ? g_csr[beg + full + lane] : 0;
        float myD = (lane < rem) ? g_dinv[myS] : 0.f;
        for (int j = 0; j < rem; j++) {
            int   s = __shfl_sync(0xffffffffu, myS, j);
            float w = __shfl_sync(0xffffffffu, myD, j);
            float4 v = base[(size_t)s * 32 + lane];
            acc.x += w * v.x; acc.y += w * v.y;
            acc.z += w * v.z; acc.w += w * v.w;
        }
    }
    float4 bb = ((const float4*)b1)[lane];
    float4 h;
    float vx = dv * acc.x + bb.x; h.x = vx > 0.f ? vx : expm1f(vx);
    float vy = dv * acc.y + bb.y; h.y = vy > 0.f ? vy : expm1f(vy);
    float vz = dv * acc.z + bb.z; h.z = vz > 0.f ? vz : expm1f(vz);
    float vw = dv * acc.w + bb.w; h.w = vw > 0.f ? vw : expm1f(vw);
    ((float4*)g_h)[(size_t)i * 32 + lane] = h;
}

// ------- pool1: run-length batched atomics into msum1 + graph counts ---------
__global__ void __launch_bounds__(128) pool1_kernel(const void* __restrict__ batch, int N) {
    int j = threadIdx.x;
    int base = blockIdx.x * 64;
    int is64 = g_is64_batch;
    float acc = 0.f; int curg = -1; int runcnt = 0;
    for (int r = 0; r < 64; r++) {
        int i = base + r;
        if (i >= N) break;
        float hv = g_h[(size_t)i * 128 + j];
        int g = (int)ld_idx(batch, i, is64);
        if (g != curg) {
            if (curg >= 0) {
                atomicAdd(&g_msum1[curg * HDIM + j], acc);
                if (j == 0) atomicAdd(&g_cnt[curg], (float)runcnt);
            }
            acc = 0.f; runcnt = 0; curg = g;
        }
        acc += hv; runcnt++;
    }
    if (curg >= 0) {
        atomicAdd(&g_msum1[curg * HDIM + j], acc);
        if (j == 0) atomicAdd(&g_cnt[curg], (float)runcnt);
    }
}

// ---------------- master1: r1 = relu(mean_pool(h) @ mW1 + mb1) ---------------
__global__ void master1_kernel(const float* __restrict__ mW1,
                               const float* __restrict__ mb1) {
    __shared__ float m[HDIM];
    int g = blockIdx.x, j = threadIdx.x;
    float c = fmaxf(g_cnt[g], 1.f);
    m[j] = g_msum1[g * HDIM + j] / c;
    __syncthreads();
    float a = mb1[j];
#pragma unroll 4
    for (int k = 0; k < HDIM; k++) a += m[k] * mW1[k * HDIM + j];
    g_r1[g * HDIM + j] = fmaxf(a, 0.f);
}

// ---------------- GEMM2: y2 = dinv .* ((h + r1[batch]) @ W2)  [N,32] ---------
__global__ void __launch_bounds__(128) gemm2_kernel(
    const void* __restrict__ batch, const float* __restrict__ W2, int N)
{
    __shared__ float Ws[128 * 32];
    int t = threadIdx.x;
#pragma unroll
    for (int u = 0; u < 8; u++) {
        int idx = u * 512 + t * 4;
        *(float4*)&Ws[idx] = *(const float4*)&W2[idx];
    }
    __syncthreads();
    int i = blockIdx.x * 128 + t;
    if (i >= N) return;
    int g = (int)ld_idx(batch, i, g_is64_batch);
    const float* hr = g_h + (size_t)i * 128;
    const float* rr = g_r1 + g * 128;
    float4 acc[8];
#pragma unroll
    for (int j = 0; j < 8; j++) acc[j] = make_float4(0.f, 0.f, 0.f, 0.f);
#pragma unroll 2
    for (int k0 = 0; k0 < 128; k0 += 4) {
        float4 xv = *(const float4*)(hr + k0);
        float4 rv = *(const float4*)(rr + k0);
        float xs[4] = {xv.x + rv.x, xv.y + rv.y, xv.z + rv.z, xv.w + rv.w};
#pragma unroll
        for (int kk = 0; kk < 4; kk++) {
            const float4* wrow = (const float4*)&Ws[(k0 + kk) * 32];
            float x = xs[kk];
#pragma unroll
            for (int j = 0; j < 8; j++) {
                float4 w = wrow[j];
                acc[j].x += x * w.x; acc[j].y += x * w.y;
                acc[j].z += x * w.z; acc[j].w += x * w.w;
            }
        }
    }
    float dv = g_dinv[i];
#pragma unroll
    for (int j = 0; j < 8; j++) {
        float4 v = acc[j];
        v.x *= dv; v.y *= dv; v.z *= dv; v.w *= dv;
        *(float4*)(g_y2 + (size_t)i * 32 + j * 4) = v;
    }
}

// ----- agg2 (gather) + epilogue: Z = dinv*(self + sum_nbrs) + b2 -------------
__global__ void __launch_bounds__(256) agg2_kernel(const float* __restrict__ b2, int N) {
    int warp = (blockIdx.x * blockDim.x + threadIdx.x) >> 5;
    int lane = threadIdx.x & 31;
    if (warp >= N) return;
    int i = warp;
    int beg  = g_rowstart[i];
    int cntE = g_cnt_i[i];
    float acc = g_y2[(size_t)i * 32 + lane];    // self loop (pre-scaled)
    int full = cntE & ~31;
    for (int k = 0; k < full; k += 32) {
        int myS = g_csr[beg + k + lane];
#pragma unroll 8
        for (int j = 0; j < 32; j++) {
            int s = __shfl_sync(0xffffffffu, myS, j);
            acc += g_y2[(size_t)s * 32 + lane];
        }
    }
    int rem = cntE - full;
    if (rem) {
        int myS = (lane < rem) ? g_csr[beg + full + lane] : 0;
        for (int j = 0; j < rem; j++) {
            int s = __shfl_sync(0xffffffffu, myS, j);
            acc += g_y2[(size_t)s * 32 + lane];
        }
    }
    g_z[(size_t)i * 32 + lane] = g_dinv[i] * acc + b2[lane];
}

// ------- pool2: run-length batched atomics into msum2 ------------------------
__global__ void __launch_bounds__(128) pool2_kernel(const void* __restrict__ batch, int N) {
    int j = threadIdx.x & 31;
    int seg = threadIdx.x >> 5;                // 4 warps per block
    int base = blockIdx.x * 256 + seg * 64;
    int is64 = g_is64_batch;
    float acc = 0.f; int curg = -1;
    for (int r = 0; r < 64; r++) {
        int i = base + r;
        if (i >= N) break;
        float zv = g_z[(size_t)i * 32 + j];
        int g = (int)ld_idx(batch, i, is64);
        if (g != curg) {
            if (curg >= 0) atomicAdd(&g_msum2[curg * KDIM + j], acc);
            acc = 0.f; curg = g;
        }
        acc += zv;
    }
    if (curg >= 0) atomicAdd(&g_msum2[curg * KDIM + j], acc);
}

// ---------------- master2: r2 = relu(mean_pool(Z) @ mW2 + mb2) ---------------
__global__ void master2_kernel(const float* __restrict__ mW2,
                               const float* __restrict__ mb2) {
    __shared__ float m[KDIM];
    int g = blockIdx.x, j = threadIdx.x;
    float c = fmaxf(g_cnt[g], 1.f);
    m[j] = g_msum2[g * KDIM + j] / c;
    __syncthreads();
    float a = mb2[j];
#pragma unroll
    for (int k = 0; k < KDIM; k++) a += m[k] * mW2[k * KDIM + j];
    g_r2[g * KDIM + j] = fmaxf(a, 0.f);
}

// ---------------- softmax over 32 cols (1 warp per row) ----------------------
__global__ void softmax_kernel(const void* __restrict__ batch,
                               float* __restrict__ out, int N) {
    int gtid = blockIdx.x * blockDim.x + threadIdx.x;
    int i = gtid >> 5;
    int j = threadIdx.x & 31;
    if (i >= N) return;
    int g = (int)ld_idx(batch, i, g_is64_batch);
    float z = g_z[(size_t)i * 32 + j] + g_r2[g * 32 + j];
    float m = z;
#pragma unroll
    for (int o = 16; o > 0; o >>= 1) m = fmaxf(m, __shfl_xor_sync(0xffffffffu, m, o));
    float e = __expf(z - m);
    float s = e;
#pragma unroll
    for (int o = 16; o > 0; o >>= 1) s += __shfl_xor_sync(0xffffffffu, s, o);
    out[(size_t)i * 32 + j] = e / s;
}

// ---------------- launch ------------------------------------------------------
extern "C" void kernel_launch(void* const* d_in, const int* in_sizes, int n_in,
                              void* d_out, int out_size) {
    const float* X   = (const float*)d_in[0];
    const float* W1  = (const float*)d_in[1];
    const float* b1  = (const float*)d_in[2];
    const float* W2  = (const float*)d_in[3];
    const float* b2  = (const float*)d_in[4];
    const float* mW1 = (const float*)d_in[5];
    const float* mb1 = (const float*)d_in[6];
    const float* mW2 = (const float*)d_in[7];
    const float* mb2 = (const float*)d_in[8];
    const void*  ei  = d_in[9];
    const void*  bat = d_in[10];

    int N = in_sizes[0] / FDIM;
    long long E = in_sizes[9] / 2;
    float* out = (float*)d_out;

    int nScanBlocks = (N + 1023) / 1024;

    // Lazily-created side stream + events for a graph fork (gemm1 || CSR build).
    static cudaStream_t s2 = nullptr;
    static cudaEvent_t evFork = nullptr, evJoin = nullptr;
    static int tried = 0;
    if (!tried) {
        tried = 1;
        if (cudaStreamCreateWithFlags(&s2, cudaStreamNonBlocking) != cudaSuccess) s2 = nullptr;
        if (s2) {
            if (cudaEventCreateWithFlags(&evFork, cudaEventDisableTiming) != cudaSuccess ||
                cudaEventCreateWithFlags(&evJoin, cudaEventDisableTiming) != cudaSuccess) {
                s2 = nullptr;
            }
        }
    }

    if (s2) {
        cudaEventRecord(evFork, 0);
        cudaStreamWaitEvent(s2, evFork, 0);
        gemm1_kernel<<<(N + 63) / 64, 128, 0, s2>>>(X, W1, N);
        cudaEventRecord(evJoin, s2);
    }

    detect_kernel<<<1, 32>>>(ei, bat, E, N);
    init_kernel<<<(GMAX * HDIM + 255) / 256 > (N + 255) / 256 ?
                  (GMAX * HDIM + 255) / 256 : (N + 255) / 256, 256>>>(N);
    hist_kernel<<<(int)((E + 255) / 256), 256>>>(ei, E);
    scan1_kernel<<<nScanBlocks, 1024>>>(N);
    scan2_kernel<<<1, 32>>>(nScanBlocks);
    scan3_kernel<<<(N + 255) / 256, 256>>>(N);
    fill_kernel<<<(int)((E + 255) / 256), 256>>>(E);

    if (s2) {
        cudaStreamWaitEvent(0, evJoin, 0);
    } else {
        gemm1_kernel<<<(N + 63) / 64, 128>>>(X, W1, N);
    }

    agg1_kernel<<<(N * 32 + 255) / 256, 256>>>(b1, N);
    pool1_kernel<<<(N + 63) / 64, 128>>>(bat, N);
    master1_kernel<<<GMAX, HDIM>>>(mW1, mb1);
    gemm2_kernel<<<(N + 127) / 128, 128>>>(bat, W2, N);
    agg2_kernel<<<(N * 32 + 255) / 256, 256>>>(b2, N);
    pool2_kernel<<<(N + 255) / 256, 128>>>(bat, N);
    master2_kernel<<<GMAX, KDIM>>>(mW2, mb2);
    softmax_kernel<<<(N * 32 + 255) / 256, 256>>>(bat, out, N);
}

// round 4
// speedup vs baseline: 1.6554x; 1.0906x over previous
#include <cuda_runtime.h>
#include <cuda_bf16.h>
#include <math.h>

#define NMAX  50176
#define EMAX  1664000
#define GMAX  64
#define FDIM  128
#define HDIM  128
#define KDIM  32

// ---------------- scratch (static device globals; no allocation) -------------
__device__ float g_dinv[NMAX];
__device__ float g_y1  [NMAX * HDIM];   // xw = X@W1 (UNSCALED fp32)
__device__ uint2 g_y1b [NMAX * 32];     // bf16(dinv*xw): 4 bf16 per uint2, 256B/row
__device__ float g_h   [NMAX * HDIM];   // h after conv1 epilogue
__device__ float g_y2  [NMAX * KDIM];   // y2 = dinv*((h+r1)@W2)
__device__ float g_z   [NMAX * KDIM];   // Z after conv2 epilogue
__device__ float g_msum1[GMAX * HDIM];
__device__ float g_r1  [GMAX * HDIM];
__device__ float g_msum2[GMAX * KDIM];
__device__ float g_r2  [GMAX * KDIM];
__device__ float g_cnt [GMAX];
__device__ int   g_cnt_i[NMAX];        // in-degree (without self loop)
__device__ int   g_rowstart[NMAX];
__device__ int   g_cursor[NMAX];
__device__ int   g_bsums[64];
__device__ int   g_src32[EMAX];
__device__ int   g_dst32[EMAX];
__device__ int   g_csr  [EMAX];        // src ids sorted by dst
__device__ int   g_is64_ei;
__device__ int   g_is64_batch;

__device__ __forceinline__ long long ld_idx(const void* p, long long pos, int is64) {
    if (is64) return ((const long long*)p)[pos];
    return (long long)((const int*)p)[pos];
}

// ---------------- dtype detection (int64 vs int32, decided from data) --------
__global__ void detect_kernel(const void* ei, const void* batch, long long E, int N) {
    if (threadIdx.x != 0 || blockIdx.x != 0) return;
    const unsigned long long* p = (const unsigned long long*)ei;
    int ok = 1;
    for (int i = 0; i < 64; i++) {
        long long w = (long long)i * (E - 1) / 63;
        if (p[w] >= (unsigned long long)N) { ok = 0; break; }
    }
    g_is64_ei = ok;
    const unsigned long long* q = (const unsigned long long*)batch;
    int ok2 = 1;
    for (int i = 0; i < 64; i++) {
        long long w = (long long)(N / 2) - 1 - i;
        if (w < 0) break;
        if (q[w] >= (unsigned long long)GMAX) { ok2 = 0; break; }
    }
    g_is64_batch = ok2;
}

// ---------------- init: zero counters ----------------------------------------
__global__ void init_kernel(int N) {
    int idx = blockIdx.x * blockDim.x + threadIdx.x;
    if (idx < N)           g_cnt_i[idx] = 0;
    if (idx < GMAX * HDIM) g_msum1[idx] = 0.f;
    if (idx < GMAX * KDIM) g_msum2[idx] = 0.f;
}

// ------- per-graph node counts via binary search over sorted batch -----------
__global__ void cnt_kernel(const void* __restrict__ batch, int N) {
    int g = threadIdx.x;           // 0..63 (one block of 64+1 searches)
    if (g > GMAX) return;
    __shared__ int start[GMAX + 1];
    // first index i with batch[i] >= g
    int is64 = g_is64_batch;
    int lo = 0, hi = N;
    while (lo < hi) {
        int mid = (lo + hi) >> 1;
        int v = (int)ld_idx(batch, mid, is64);
        if (v < g) lo = mid + 1; else hi = mid;
    }
    start[g] = lo;
    __syncthreads();
    if (g < GMAX) g_cnt[g] = (float)(start[g + 1] - start[g]);
}

// ------------- histogram + convert indices to int32 --------------------------
__global__ void hist_kernel(const void* __restrict__ ei, long long E) {
    long long e = (long long)blockIdx.x * blockDim.x + threadIdx.x;
    if (e >= E) return;
    int is64 = g_is64_ei;
    int s = (int)ld_idx(ei, e, is64);
    int d = (int)ld_idx(ei, E + e, is64);
    g_src32[e] = s;
    g_dst32[e] = d;
    atomicAdd(&g_cnt_i[d], 1);
}

// ------------- prefix-sum over node counts (3 small kernels) ------------------
__global__ void scan1_kernel(int N) {
    __shared__ int sm[1024];
    int t = threadIdx.x;
    int idx = blockIdx.x * 1024 + t;
    int val = (idx < N) ? g_cnt_i[idx] : 0;
    sm[t] = val;
    __syncthreads();
    for (int off = 1; off < 1024; off <<= 1) {
        int x = (t >= off) ? sm[t - off] : 0;
        __syncthreads();
        sm[t] += x;
        __syncthreads();
    }
    if (idx < N) g_rowstart[idx] = sm[t] - val;   // exclusive, block-local
    if (t == 1023) g_bsums[blockIdx.x] = sm[1023];
}
__global__ void scan2_kernel(int nb) {
    if (threadIdx.x != 0) return;
    int run = 0;
    for (int b = 0; b < nb; b++) { int v = g_bsums[b]; g_bsums[b] = run; run += v; }
}
__global__ void scan3_kernel(int N) {
    int idx = blockIdx.x * blockDim.x + threadIdx.x;
    if (idx >= N) return;
    int v = g_rowstart[idx] + g_bsums[idx >> 10];
    g_rowstart[idx] = v;
    g_cursor[idx]   = v;
    g_dinv[idx]     = rsqrtf((float)g_cnt_i[idx] + 1.0f);   // +1 self loop
}

// ------------- scatter-fill CSR (src sorted by dst) ---------------------------
__global__ void fill_kernel(long long E) {
    long long e = (long long)blockIdx.x * blockDim.x + threadIdx.x;
    if (e >= E) return;
    int d = g_dst32[e];
    int pos = atomicAdd(&g_cursor[d], 1);
    g_csr[pos] = g_src32[e];
}

// ---------------- GEMM1: xw = X @ W1 (unscaled)  [N,128]x[128,128] -----------
__global__ void __launch_bounds__(128) gemm1_kernel(
    const float* __restrict__ X, const float* __restrict__ W, int N)
{
    __shared__ float As[16][64];
    __shared__ float Bs[16][128];
    int t  = threadIdx.x;
    int tx = t & 15;
    int ty = t >> 4;
    int rowBase = blockIdx.x * 64;

    float acc[8][8];
#pragma unroll
    for (int i = 0; i < 8; i++)
#pragma unroll
        for (int j = 0; j < 8; j++) acc[i][j] = 0.f;

    for (int k0 = 0; k0 < 128; k0 += 16) {
#pragma unroll
        for (int u = 0; u < 2; u++) {
            int idx = t * 8 + u * 4;
            int r = idx >> 4, c = idx & 15;
            int grow = rowBase + r;
            float4 v = make_float4(0.f, 0.f, 0.f, 0.f);
            if (grow < N) v = *(const float4*)(X + (size_t)grow * 128 + k0 + c);
            As[c + 0][r] = v.x; As[c + 1][r] = v.y;
            As[c + 2][r] = v.z; As[c + 3][r] = v.w;
        }
#pragma unroll
        for (int u = 0; u < 4; u++) {
            int idx = t * 16 + u * 4;
            int r = idx >> 7, c = idx & 127;
            *(float4*)&Bs[r][c] = *(const float4*)(W + (k0 + r) * 128 + c);
        }
        __syncthreads();
#pragma unroll
        for (int kk = 0; kk < 16; kk++) {
            float a[8], b[8];
            *(float4*)&a[0] = *(float4*)&As[kk][ty * 8];
            *(float4*)&a[4] = *(float4*)&As[kk][ty * 8 + 4];
            *(float4*)&b[0] = *(float4*)&Bs[kk][tx * 8];
            *(float4*)&b[4] = *(float4*)&Bs[kk][tx * 8 + 4];
#pragma unroll
            for (int i = 0; i < 8; i++)
#pragma unroll
                for (int j = 0; j < 8; j++)
                    acc[i][j] += a[i] * b[j];
        }
        __syncthreads();
    }
#pragma unroll
    for (int i = 0; i < 8; i++) {
        int grow = rowBase + ty * 8 + i;
        if (grow < N) {
#pragma unroll
            for (int j = 0; j < 8; j += 4) {
                float4 v;
                v.x = acc[i][j + 0]; v.y = acc[i][j + 1];
                v.z = acc[i][j + 2]; v.w = acc[i][j + 3];
                *(float4*)(g_y1 + (size_t)grow * 128 + tx * 8 + j) = v;
            }
        }
    }
}

// -------- scale: y1b = bf16(dinv[row] * xw[row])  (needs gemm1 + dinv) -------
__global__ void scale_kernel(int N) {
    int idx = blockIdx.x * blockDim.x + threadIdx.x;
    if (idx >= N * 32) return;
    int row = idx >> 5;
    float dv = g_dinv[row];
    float4 v = ((const float4*)g_y1)[idx];
    __nv_bfloat162 lo = __floats2bfloat162_rn(dv * v.x, dv * v.y);
    __nv_bfloat162 hi = __floats2bfloat162_rn(dv * v.z, dv * v.w);
    uint2 o;
    o.x = *(unsigned*)&lo;
    o.y = *(unsigned*)&hi;
    g_y1b[idx] = o;
}

// ----- agg1 (bf16 gather) + epilogue: h = elu(dinv*(...) + b1); fused pool ---
__global__ void __launch_bounds__(256) agg1_kernel(
    const float* __restrict__ b1, const void* __restrict__ batch, int N)
{
    int warp = (blockIdx.x * blockDim.x + threadIdx.x) >> 5;
    int lane = threadIdx.x & 31;
    if (warp >= N) return;
    int i = warp;
    int beg  = g_rowstart[i];
    int cntE = g_cnt_i[i];
    float dv = g_dinv[i];
    // self loop in fp32: dinv[i]*xw[i]
    float4 self = ((const float4*)g_y1)[(size_t)i * 32 + lane];
    float4 acc;
    acc.x = dv * self.x; acc.y = dv * self.y;
    acc.z = dv * self.z; acc.w = dv * self.w;
    int full = cntE & ~31;
    for (int k = 0; k < full; k += 32) {
        int myS = g_csr[beg + k + lane];
#pragma unroll 8
        for (int j = 0; j < 32; j++) {
            int s = __shfl_sync(0xffffffffu, myS, j);
            uint2 v = g_y1b[(size_t)s * 32 + lane];
            float2 a = __bfloat1622float2(*(__nv_bfloat162*)&v.x);
            float2 b = __bfloat1622float2(*(__nv_bfloat162*)&v.y);
            acc.x += a.x; acc.y += a.y; acc.z += b.x; acc.w += b.y;
        }
    }
    int rem = cntE - full;
    if (rem) {
        int myS = (lane < rem) ? g_csr[beg + full + lane] : 0;
        for (int j = 0; j < rem; j++) {
            int s = __shfl_sync(0xffffffffu, myS, j);
            uint2 v = g_y1b[(size_t)s * 32 + lane];
            float2 a = __bfloat1622float2(*(__nv_bfloat162*)&v.x);
            float2 b = __bfloat1622float2(*(__nv_bfloat162*)&v.y);
            acc.x += a.x; acc.y += a.y; acc.z += b.x; acc.w += b.y;
        }
    }
    float4 bb = ((const float4*)b1)[lane];
    float4 h;
    float vx = dv * acc.x + bb.x; h.x = vx > 0.f ? vx : expm1f(vx);
    float vy = dv * acc.y + bb.y; h.y = vy > 0.f ? vy : expm1f(vy);
    float vz = dv * acc.z + bb.z; h.z = vz > 0.f ? vz : expm1f(vz);
    float vw = dv * acc.w + bb.w; h.w = vw > 0.f ? vw : expm1f(vw);
    ((float4*)g_h)[(size_t)i * 32 + lane] = h;
    // fused mean-pool numerator
    int g = (int)ld_idx(batch, i, g_is64_batch);
    float* ms = g_msum1 + g * HDIM + lane * 4;
    asm volatile("red.global.add.v4.f32 [%0], {%1, %2, %3, %4};"
                 :: "l"(ms), "f"(h.x), "f"(h.y), "f"(h.z), "f"(h.w) : "memory");
}

// ---------------- master1: r1 = relu(mean_pool(h) @ mW1 + mb1) ---------------
__global__ void master1_kernel(const float* __restrict__ mW1,
                               const float* __restrict__ mb1) {
    __shared__ float m[HDIM];
    int g = blockIdx.x, j = threadIdx.x;
    float c = fmaxf(g_cnt[g], 1.f);
    m[j] = g_msum1[g * HDIM + j] / c;
    __syncthreads();
    float a = mb1[j];
#pragma unroll 4
    for (int k = 0; k < HDIM; k++) a += m[k] * mW1[k * HDIM + j];
    g_r1[g * HDIM + j] = fmaxf(a, 0.f);
}

// ---------------- GEMM2: y2 = dinv .* ((h + r1[batch]) @ W2)  [N,32] ---------
__global__ void __launch_bounds__(128) gemm2_kernel(
    const void* __restrict__ batch, const float* __restrict__ W2, int N)
{
    __shared__ float Ws[128 * 32];
    int t = threadIdx.x;
#pragma unroll
    for (int u = 0; u < 8; u++) {
        int idx = u * 512 + t * 4;
        *(float4*)&Ws[idx] = *(const float4*)&W2[idx];
    }
    __syncthreads();
    int i = blockIdx.x * 128 + t;
    if (i >= N) return;
    int g = (int)ld_idx(batch, i, g_is64_batch);
    const float* hr = g_h + (size_t)i * 128;
    const float* rr = g_r1 + g * 128;
    float4 acc[8];
#pragma unroll
    for (int j = 0; j < 8; j++) acc[j] = make_float4(0.f, 0.f, 0.f, 0.f);
#pragma unroll 2
    for (int k0 = 0; k0 < 128; k0 += 4) {
        float4 xv = *(const float4*)(hr + k0);
        float4 rv = *(const float4*)(rr + k0);
        float xs[4] = {xv.x + rv.x, xv.y + rv.y, xv.z + rv.z, xv.w + rv.w};
#pragma unroll
        for (int kk = 0; kk < 4; kk++) {
            const float4* wrow = (const float4*)&Ws[(k0 + kk) * 32];
            float x = xs[kk];
#pragma unroll
            for (int j = 0; j < 8; j++) {
                float4 w = wrow[j];
                acc[j].x += x * w.x; acc[j].y += x * w.y;
                acc[j].z += x * w.z; acc[j].w += x * w.w;
            }
        }
    }
    float dv = g_dinv[i];
#pragma unroll
    for (int j = 0; j < 8; j++) {
        float4 v = acc[j];
        v.x *= dv; v.y *= dv; v.z *= dv; v.w *= dv;
        *(float4*)(g_y2 + (size_t)i * 32 + j * 4) = v;
    }
}

// ----- agg2 (gather) + epilogue: Z = dinv*(self + sum) + b2; fused pool ------
__global__ void __launch_bounds__(256) agg2_kernel(
    const float* __restrict__ b2, const void* __restrict__ batch, int N)
{
    int warp = (blockIdx.x * blockDim.x + threadIdx.x) >> 5;
    int lane = threadIdx.x & 31;
    if (warp >= N) return;
    int i = warp;
    int beg  = g_rowstart[i];
    int cntE = g_cnt_i[i];
    float acc = g_y2[(size_t)i * 32 + lane];    // self loop (pre-scaled)
    int full = cntE & ~31;
    for (int k = 0; k < full; k += 32) {
        int myS = g_csr[beg + k + lane];
#pragma unroll 8
        for (int j = 0; j < 32; j++) {
            int s = __shfl_sync(0xffffffffu, myS, j);
            acc += g_y2[(size_t)s * 32 + lane];
        }
    }
    int rem = cntE - full;
    if (rem) {
        int myS = (lane < rem) ? g_csr[beg + full + lane] : 0;
        for (int j = 0; j < rem; j++) {
            int s = __shfl_sync(0xffffffffu, myS, j);
            acc += g_y2[(size_t)s * 32 + lane];
        }
    }
    float z = g_dinv[i] * acc + b2[lane];
    g_z[(size_t)i * 32 + lane] = z;
    int g = (int)ld_idx(batch, i, g_is64_batch);
    atomicAdd(&g_msum2[g * KDIM + lane], z);
}

// ---------------- master2: r2 = relu(mean_pool(Z) @ mW2 + mb2) ---------------
__global__ void master2_kernel(const float* __restrict__ mW2,
                               const float* __restrict__ mb2) {
    __shared__ float m[KDIM];
    int g = blockIdx.x, j = threadIdx.x;
    float c = fmaxf(g_cnt[g], 1.f);
    m[j] = g_msum2[g * KDIM + j] / c;
    __syncthreads();
    float a = mb2[j];
#pragma unroll
    for (int k = 0; k < KDIM; k++) a += m[k] * mW2[k * KDIM + j];
    g_r2[g * KDIM + j] = fmaxf(a, 0.f);
}

// ---------------- softmax over 32 cols (1 warp per row) ----------------------
__global__ void softmax_kernel(const void* __restrict__ batch,
                               float* __restrict__ out, int N) {
    int gtid = blockIdx.x * blockDim.x + threadIdx.x;
    int i = gtid >> 5;
    int j = threadIdx.x & 31;
    if (i >= N) return;
    int g = (int)ld_idx(batch, i, g_is64_batch);
    float z = g_z[(size_t)i * 32 + j] + g_r2[g * 32 + j];
    float m = z;
#pragma unroll
    for (int o = 16; o > 0; o >>= 1) m = fmaxf(m, __shfl_xor_sync(0xffffffffu, m, o));
    float e = __expf(z - m);
    float s = e;
#pragma unroll
    for (int o = 16; o > 0; o >>= 1) s += __shfl_xor_sync(0xffffffffu, s, o);
    out[(size_t)i * 32 + j] = e / s;
}

// ---------------- launch ------------------------------------------------------
extern "C" void kernel_launch(void* const* d_in, const int* in_sizes, int n_in,
                              void* d_out, int out_size) {
    const float* X   = (const float*)d_in[0];
    const float* W1  = (const float*)d_in[1];
    const float* b1  = (const float*)d_in[2];
    const float* W2  = (const float*)d_in[3];
    const float* b2  = (const float*)d_in[4];
    const float* mW1 = (const float*)d_in[5];
    const float* mb1 = (const float*)d_in[6];
    const float* mW2 = (const float*)d_in[7];
    const float* mb2 = (const float*)d_in[8];
    const void*  ei  = d_in[9];
    const void*  bat = d_in[10];

    int N = in_sizes[0] / FDIM;
    long long E = in_sizes[9] / 2;
    float* out = (float*)d_out;

    int nScanBlocks = (N + 1023) / 1024;

    // Lazily-created side stream + events for a graph fork (gemm1 || CSR build).
    static cudaStream_t s2 = nullptr;
    static cudaEvent_t evFork = nullptr, evJoin = nullptr;
    static int tried = 0;
    if (!tried) {
        tried = 1;
        if (cudaStreamCreateWithFlags(&s2, cudaStreamNonBlocking) != cudaSuccess) s2 = nullptr;
        if (s2) {
            if (cudaEventCreateWithFlags(&evFork, cudaEventDisableTiming) != cudaSuccess ||
                cudaEventCreateWithFlags(&evJoin, cudaEventDisableTiming) != cudaSuccess) {
                s2 = nullptr;
            }
        }
    }

    if (s2) {
        cudaEventRecord(evFork, 0);
        cudaStreamWaitEvent(s2, evFork, 0);
        gemm1_kernel<<<(N + 63) / 64, 128, 0, s2>>>(X, W1, N);
        cudaEventRecord(evJoin, s2);
    }

    detect_kernel<<<1, 32>>>(ei, bat, E, N);
    init_kernel<<<(GMAX * HDIM + 255) / 256 > (N + 255) / 256 ?
                  (GMAX * HDIM + 255) / 256 : (N + 255) / 256, 256>>>(N);
    cnt_kernel<<<1, GMAX + 1>>>(bat, N);
    hist_kernel<<<(int)((E + 255) / 256), 256>>>(ei, E);
    scan1_kernel<<<nScanBlocks, 1024>>>(N);
    scan2_kernel<<<1, 32>>>(nScanBlocks);
    scan3_kernel<<<(N + 255) / 256, 256>>>(N);
    fill_kernel<<<(int)((E + 255) / 256), 256>>>(E);

    if (s2) {
        cudaStreamWaitEvent(0, evJoin, 0);
    } else {
        gemm1_kernel<<<(N + 63) / 64, 128>>>(X, W1, N);
    }

    scale_kernel<<<(N * 32 + 255) / 256, 256>>>(N);
    agg1_kernel<<<(N * 32 + 255) / 256, 256>>>(b1, bat, N);
    master1_kernel<<<GMAX, HDIM>>>(mW1, mb1);
    gemm2_kernel<<<(N + 127) / 128, 128>>>(bat, W2, N);
    agg2_kernel<<<(N * 32 + 255) / 256, 256>>>(b2, bat, N);
    master2_kernel<<<GMAX, KDIM>>>(mW2, mb2);
    softmax_kernel<<<(N * 32 + 255) / 256, 256>>>(bat, out, N);
}

// round 5
// speedup vs baseline: 1.6683x; 1.0078x over previous
#include <cuda_runtime.h>
#include <cuda_bf16.h>
#include <math.h>

#define NMAX  50176
#define EMAX  1664000
#define GMAX  64
#define FDIM  128
#define HDIM  128
#define KDIM  32

// ---------------- scratch (static device globals; no allocation) -------------
__device__ float g_dinv[NMAX];
__device__ float g_y1  [NMAX * HDIM];   // xw = X@W1 (UNSCALED fp32)
__device__ uint2 g_y1b [NMAX * 32];     // bf16(dinv*xw): 4 bf16 per uint2, 256B/row
__device__ float g_h   [NMAX * HDIM];   // h after conv1 epilogue
__device__ float g_y2  [NMAX * KDIM];   // y2 = dinv*((h+r1)@W2)  (fp32)
__device__ unsigned short g_y2b[NMAX * KDIM];  // bf16 copy of y2, 64B/row
__device__ float g_z   [NMAX * KDIM];   // Z after conv2 epilogue
__device__ float g_msum1[GMAX * HDIM];
__device__ float g_r1  [GMAX * HDIM];
__device__ float g_msum2[GMAX * KDIM];
__device__ float g_r2  [GMAX * KDIM];
__device__ float g_cnt [GMAX];
__device__ int   g_cnt_i[NMAX];        // in-degree (without self loop)
__device__ int   g_rowstart[NMAX];
__device__ int   g_cursor[NMAX];
__device__ int   g_bsums[64];
__device__ int   g_csr  [EMAX];        // src ids sorted by dst
__device__ int   g_is64_ei;
__device__ int   g_is64_batch;

__device__ __forceinline__ long long ld_idx(const void* p, long long pos, int is64) {
    if (is64) return ((const long long*)p)[pos];
    return (long long)((const int*)p)[pos];
}

// ---------------- dtype detection (int64 vs int32, decided from data) --------
__global__ void detect_kernel(const void* ei, const void* batch, long long E, int N) {
    if (threadIdx.x != 0 || blockIdx.x != 0) return;
    const unsigned long long* p = (const unsigned long long*)ei;
    int ok = 1;
    for (int i = 0; i < 64; i++) {
        long long w = (long long)i * (E - 1) / 63;
        if (p[w] >= (unsigned long long)N) { ok = 0; break; }
    }
    g_is64_ei = ok;
    const unsigned long long* q = (const unsigned long long*)batch;
    int ok2 = 1;
    for (int i = 0; i < 64; i++) {
        long long w = (long long)(N / 2) - 1 - i;
        if (w < 0) break;
        if (q[w] >= (unsigned long long)GMAX) { ok2 = 0; break; }
    }
    g_is64_batch = ok2;
}

// detect only the batch dtype (side-stream copy, no ordering vs main detect) --
__global__ void detect_batch_kernel(const void* batch, int N) {
    if (threadIdx.x != 0) return;
    const unsigned long long* q = (const unsigned long long*)batch;
    int ok2 = 1;
    for (int i = 0; i < 64; i++) {
        long long w = (long long)(N / 2) - 1 - i;
        if (w < 0) break;
        if (q[w] >= (unsigned long long)GMAX) { ok2 = 0; break; }
    }
    g_is64_batch = ok2;
}

// ---------------- init: zero counters ----------------------------------------
__global__ void init_kernel(int N) {
    int idx = blockIdx.x * blockDim.x + threadIdx.x;
    if (idx < N)           g_cnt_i[idx] = 0;
    if (idx < GMAX * HDIM) g_msum1[idx] = 0.f;
    if (idx < GMAX * KDIM) g_msum2[idx] = 0.f;
}

// ------- per-graph node counts via binary search over sorted batch -----------
__global__ void cnt_kernel(const void* __restrict__ batch, int N) {
    int g = threadIdx.x;           // 0..64 (one block of 65 searches)
    if (g > GMAX) return;
    __shared__ int start[GMAX + 1];
    int is64 = g_is64_batch;
    int lo = 0, hi = N;
    while (lo < hi) {
        int mid = (lo + hi) >> 1;
        int v = (int)ld_idx(batch, mid, is64);
        if (v < g) lo = mid + 1; else hi = mid;
    }
    start[g] = lo;
    __syncthreads();
    if (g < GMAX) g_cnt[g] = (float)(start[g + 1] - start[g]);
}

// ------------- degree histogram (reads only dst half of ei) ------------------
__global__ void hist_kernel(const void* __restrict__ ei, long long E) {
    long long e = (long long)blockIdx.x * blockDim.x + threadIdx.x;
    if (e >= E) return;
    int d = (int)ld_idx(ei, E + e, g_is64_ei);
    atomicAdd(&g_cnt_i[d], 1);
}

// ------------- prefix-sum over node counts (3 small kernels) ------------------
__global__ void scan1_kernel(int N) {
    __shared__ int sm[1024];
    int t = threadIdx.x;
    int idx = blockIdx.x * 1024 + t;
    int val = (idx < N) ? g_cnt_i[idx] : 0;
    sm[t] = val;
    __syncthreads();
    for (int off = 1; off < 1024; off <<= 1) {
        int x = (t >= off) ? sm[t - off] : 0;
        __syncthreads();
        sm[t] += x;
        __syncthreads();
    }
    if (idx < N) g_rowstart[idx] = sm[t] - val;   // exclusive, block-local
    if (t == 1023) g_bsums[blockIdx.x] = sm[1023];
}
__global__ void scan2_kernel(int nb) {
    if (threadIdx.x != 0) return;
    int run = 0;
    for (int b = 0; b < nb; b++) { int v = g_bsums[b]; g_bsums[b] = run; run += v; }
}
__global__ void scan3_kernel(int N) {
    int idx = blockIdx.x * blockDim.x + threadIdx.x;
    if (idx >= N) return;
    int v = g_rowstart[idx] + g_bsums[idx >> 10];
    g_rowstart[idx] = v;
    g_cursor[idx]   = v;
    g_dinv[idx]     = rsqrtf((float)g_cnt_i[idx] + 1.0f);   // +1 self loop
}

// ------------- scatter-fill CSR directly from ei ------------------------------
__global__ void fill_kernel(const void* __restrict__ ei, long long E) {
    long long e = (long long)blockIdx.x * blockDim.x + threadIdx.x;
    if (e >= E) return;
    int is64 = g_is64_ei;
    int s = (int)ld_idx(ei, e, is64);
    int d = (int)ld_idx(ei, E + e, is64);
    int pos = atomicAdd(&g_cursor[d], 1);
    g_csr[pos] = s;
}

// ---------------- GEMM1: xw = X @ W1 (unscaled)  [N,128]x[128,128] -----------
__global__ void __launch_bounds__(128) gemm1_kernel(
    const float* __restrict__ X, const float* __restrict__ W, int N)
{
    __shared__ float As[16][64];
    __shared__ float Bs[16][128];
    int t  = threadIdx.x;
    int tx = t & 15;
    int ty = t >> 4;
    int rowBase = blockIdx.x * 64;

    float acc[8][8];
#pragma unroll
    for (int i = 0; i < 8; i++)
#pragma unroll
        for (int j = 0; j < 8; j++) acc[i][j] = 0.f;

    for (int k0 = 0; k0 < 128; k0 += 16) {
#pragma unroll
        for (int u = 0; u < 2; u++) {
            int idx = t * 8 + u * 4;
            int r = idx >> 4, c = idx & 15;
            int grow = rowBase + r;
            float4 v = make_float4(0.f, 0.f, 0.f, 0.f);
            if (grow < N) v = *(const float4*)(X + (size_t)grow * 128 + k0 + c);
            As[c + 0][r] = v.x; As[c + 1][r] = v.y;
            As[c + 2][r] = v.z; As[c + 3][r] = v.w;
        }
#pragma unroll
        for (int u = 0; u < 4; u++) {
            int idx = t * 16 + u * 4;
            int r = idx >> 7, c = idx & 127;
            *(float4*)&Bs[r][c] = *(const float4*)(W + (k0 + r) * 128 + c);
        }
        __syncthreads();
#pragma unroll
        for (int kk = 0; kk < 16; kk++) {
            float a[8], b[8];
            *(float4*)&a[0] = *(float4*)&As[kk][ty * 8];
            *(float4*)&a[4] = *(float4*)&As[kk][ty * 8 + 4];
            *(float4*)&b[0] = *(float4*)&Bs[kk][tx * 8];
            *(float4*)&b[4] = *(float4*)&Bs[kk][tx * 8 + 4];
#pragma unroll
            for (int i = 0; i < 8; i++)
#pragma unroll
                for (int j = 0; j < 8; j++)
                    acc[i][j] += a[i] * b[j];
        }
        __syncthreads();
    }
#pragma unroll
    for (int i = 0; i < 8; i++) {
        int grow = rowBase + ty * 8 + i;
        if (grow < N) {
#pragma unroll
            for (int j = 0; j < 8; j += 4) {
                float4 v;
                v.x = acc[i][j + 0]; v.y = acc[i][j + 1];
                v.z = acc[i][j + 2]; v.w = acc[i][j + 3];
                *(float4*)(g_y1 + (size_t)grow * 128 + tx * 8 + j) = v;
            }
        }
    }
}

// -------- scale: y1b = bf16(dinv[row] * xw[row])  (needs gemm1 + dinv) -------
__global__ void scale_kernel(int N) {
    int idx = blockIdx.x * blockDim.x + threadIdx.x;
    if (idx >= N * 32) return;
    int row = idx >> 5;
    float dv = g_dinv[row];
    float4 v = ((const float4*)g_y1)[idx];
    __nv_bfloat162 lo = __floats2bfloat162_rn(dv * v.x, dv * v.y);
    __nv_bfloat162 hi = __floats2bfloat162_rn(dv * v.z, dv * v.w);
    uint2 o;
    o.x = *(unsigned*)&lo;
    o.y = *(unsigned*)&hi;
    g_y1b[idx] = o;
}

// ----- agg1 (bf16 gather) + epilogue: h = elu(dinv*(...) + b1); fused pool ---
__global__ void __launch_bounds__(256) agg1_kernel(
    const float* __restrict__ b1, const void* __restrict__ batch, int N)
{
    int warp = (blockIdx.x * blockDim.x + threadIdx.x) >> 5;
    int lane = threadIdx.x & 31;
    if (warp >= N) return;
    int i = warp;
    int beg  = g_rowstart[i];
    int cntE = g_cnt_i[i];
    float dv = g_dinv[i];
    float4 self = ((const float4*)g_y1)[(size_t)i * 32 + lane];
    float4 acc;
    acc.x = dv * self.x; acc.y = dv * self.y;
    acc.z = dv * self.z; acc.w = dv * self.w;
    int full = cntE & ~31;
    for (int k = 0; k < full; k += 32) {
        int myS = g_csr[beg + k + lane];
#pragma unroll 8
        for (int j = 0; j < 32; j++) {
            int s = __shfl_sync(0xffffffffu, myS, j);
            uint2 v = g_y1b[(size_t)s * 32 + lane];
            float2 a = __bfloat1622float2(*(__nv_bfloat162*)&v.x);
            float2 b = __bfloat1622float2(*(__nv_bfloat162*)&v.y);
            acc.x += a.x; acc.y += a.y; acc.z += b.x; acc.w += b.y;
        }
    }
    int rem = cntE - full;
    if (rem) {
        int myS = (lane < rem) ? g_csr[beg + full + lane] : 0;
        for (int j = 0; j < rem; j++) {
            int s = __shfl_sync(0xffffffffu, myS, j);
            uint2 v = g_y1b[(size_t)s * 32 + lane];
            float2 a = __bfloat1622float2(*(__nv_bfloat162*)&v.x);
            float2 b = __bfloat1622float2(*(__nv_bfloat162*)&v.y);
            acc.x += a.x; acc.y += a.y; acc.z += b.x; acc.w += b.y;
        }
    }
    float4 bb = ((const float4*)b1)[lane];
    float4 h;
    float vx = dv * acc.x + bb.x; h.x = vx > 0.f ? vx : expm1f(vx);
    float vy = dv * acc.y + bb.y; h.y = vy > 0.f ? vy : expm1f(vy);
    float vz = dv * acc.z + bb.z; h.z = vz > 0.f ? vz : expm1f(vz);
    float vw = dv * acc.w + bb.w; h.w = vw > 0.f ? vw : expm1f(vw);
    ((float4*)g_h)[(size_t)i * 32 + lane] = h;
    int g = (int)ld_idx(batch, i, g_is64_batch);
    float* ms = g_msum1 + g * HDIM + lane * 4;
    asm volatile("red.global.add.v4.f32 [%0], {%1, %2, %3, %4};"
                 :: "l"(ms), "f"(h.x), "f"(h.y), "f"(h.z), "f"(h.w) : "memory");
}

// ---------------- master1: r1 = relu(mean_pool(h) @ mW1 + mb1) ---------------
__global__ void master1_kernel(const float* __restrict__ mW1,
                               const float* __restrict__ mb1) {
    __shared__ float m[HDIM];
    int g = blockIdx.x, j = threadIdx.x;
    float c = fmaxf(g_cnt[g], 1.f);
    m[j] = g_msum1[g * HDIM + j] / c;
    __syncthreads();
    float a = mb1[j];
#pragma unroll 4
    for (int k = 0; k < HDIM; k++) a += m[k] * mW1[k * HDIM + j];
    g_r1[g * HDIM + j] = fmaxf(a, 0.f);
}

// ------- GEMM2: y2 = dinv.*((h + r1[batch]) @ W2); also bf16 copy y2b --------
__global__ void __launch_bounds__(128) gemm2_kernel(
    const void* __restrict__ batch, const float* __restrict__ W2, int N)
{
    __shared__ float Ws[128 * 32];
    int t = threadIdx.x;
#pragma unroll
    for (int u = 0; u < 8; u++) {
        int idx = u * 512 + t * 4;
        *(float4*)&Ws[idx] = *(const float4*)&W2[idx];
    }
    __syncthreads();
    int i = blockIdx.x * 128 + t;
    if (i >= N) return;
    int g = (int)ld_idx(batch, i, g_is64_batch);
    const float* hr = g_h + (size_t)i * 128;
    const float* rr = g_r1 + g * 128;
    float4 acc[8];
#pragma unroll
    for (int j = 0; j < 8; j++) acc[j] = make_float4(0.f, 0.f, 0.f, 0.f);
#pragma unroll 2
    for (int k0 = 0; k0 < 128; k0 += 4) {
        float4 xv = *(const float4*)(hr + k0);
        float4 rv = *(const float4*)(rr + k0);
        float xs[4] = {xv.x + rv.x, xv.y + rv.y, xv.z + rv.z, xv.w + rv.w};
#pragma unroll
        for (int kk = 0; kk < 4; kk++) {
            const float4* wrow = (const float4*)&Ws[(k0 + kk) * 32];
            float x = xs[kk];
#pragma unroll
            for (int j = 0; j < 8; j++) {
                float4 w = wrow[j];
                acc[j].x += x * w.x; acc[j].y += x * w.y;
                acc[j].z += x * w.z; acc[j].w += x * w.w;
            }
        }
    }
    float dv = g_dinv[i];
    unsigned bpack[8];
#pragma unroll
    for (int j = 0; j < 8; j++) {
        float4 v = acc[j];
        v.x *= dv; v.y *= dv; v.z *= dv; v.w *= dv;
        *(float4*)(g_y2 + (size_t)i * 32 + j * 4) = v;
        __nv_bfloat162 lo = __floats2bfloat162_rn(v.x, v.y);
        __nv_bfloat162 hi = __floats2bfloat162_rn(v.z, v.w);
        bpack[j] = 0;  // placate compiler; overwritten below
        bpack[j] = *(unsigned*)&lo;
        // store hi in the following slot via local array trick
        // (we pack 2 unsigneds per float4 => 8 float4 -> 16 unsigned = 64B)
        // handled by writing both here:
        ((unsigned*)0 == 0) ? void(0) : void(0);
        // write directly:
        unsigned* dstb = (unsigned*)(g_y2b + (size_t)i * 32 + j * 4);
        dstb[0] = *(unsigned*)&lo;
        dstb[1] = *(unsigned*)&hi;
    }
    (void)bpack;
}

// ----- agg2 (bf16 gather) + epilogue: Z = dinv*(self + sum) + b2; fused pool -
__global__ void __launch_bounds__(256) agg2_kernel(
    const float* __restrict__ b2, const void* __restrict__ batch, int N)
{
    int warp = (blockIdx.x * blockDim.x + threadIdx.x) >> 5;
    int lane = threadIdx.x & 31;
    if (warp >= N) return;
    int i = warp;
    int beg  = g_rowstart[i];
    int cntE = g_cnt_i[i];
    float acc = g_y2[(size_t)i * 32 + lane];    // self loop in fp32 (pre-scaled)
    int full = cntE & ~31;
    for (int k = 0; k < full; k += 32) {
        int myS = g_csr[beg + k + lane];
#pragma unroll 8
        for (int j = 0; j < 32; j++) {
            int s = __shfl_sync(0xffffffffu, myS, j);
            unsigned short raw = g_y2b[(size_t)s * 32 + lane];
            acc += __bfloat162float(*(__nv_bfloat16*)&raw);
        }
    }
    int rem = cntE - full;
    if (rem) {
        int myS = (lane < rem) ? g_csr[beg + full + lane] : 0;
        for (int j = 0; j < rem; j++) {
            int s = __shfl_sync(0xffffffffu, myS, j);
            unsigned short raw = g_y2b[(size_t)s * 32 + lane];
            acc += __bfloat162float(*(__nv_bfloat16*)&raw);
        }
    }
    float z = g_dinv[i] * acc + b2[lane];
    g_z[(size_t)i * 32 + lane] = z;
    int g = (int)ld_idx(batch, i, g_is64_batch);
    atomicAdd(&g_msum2[g * KDIM + lane], z);
}

// ---------------- master2: r2 = relu(mean_pool(Z) @ mW2 + mb2) ---------------
__global__ void master2_kernel(const float* __restrict__ mW2,
                               const float* __restrict__ mb2) {
    __shared__ float m[KDIM];
    int g = blockIdx.x, j = threadIdx.x;
    float c = fmaxf(g_cnt[g], 1.f);
    m[j] = g_msum2[g * KDIM + j] / c;
    __syncthreads();
    float a = mb2[j];
#pragma unroll
    for (int k = 0; k < KDIM; k++) a += m[k] * mW2[k * KDIM + j];
    g_r2[g * KDIM + j] = fmaxf(a, 0.f);
}

// ---------------- softmax over 32 cols (1 warp per row) ----------------------
__global__ void softmax_kernel(const void* __restrict__ batch,
                               float* __restrict__ out, int N) {
    int gtid = blockIdx.x * blockDim.x + threadIdx.x;
    int i = gtid >> 5;
    int j = threadIdx.x & 31;
    if (i >= N) return;
    int g = (int)ld_idx(batch, i, g_is64_batch);
    float z = g_z[(size_t)i * 32 + j] + g_r2[g * 32 + j];
    float m = z;
#pragma unroll
    for (int o = 16; o > 0; o >>= 1) m = fmaxf(m, __shfl_xor_sync(0xffffffffu, m, o));
    float e = __expf(z - m);
    float s = e;
#pragma unroll
    for (int o = 16; o > 0; o >>= 1) s += __shfl_xor_sync(0xffffffffu, s, o);
    out[(size_t)i * 32 + j] = e / s;
}

// ---------------- launch ------------------------------------------------------
extern "C" void kernel_launch(void* const* d_in, const int* in_sizes, int n_in,
                              void* d_out, int out_size) {
    const float* X   = (const float*)d_in[0];
    const float* W1  = (const float*)d_in[1];
    const float* b1  = (const float*)d_in[2];
    const float* W2  = (const float*)d_in[3];
    const float* b2  = (const float*)d_in[4];
    const float* mW1 = (const float*)d_in[5];
    const float* mb1 = (const float*)d_in[6];
    const float* mW2 = (const float*)d_in[7];
    const float* mb2 = (const float*)d_in[8];
    const void*  ei  = d_in[9];
    const void*  bat = d_in[10];

    int N = in_sizes[0] / FDIM;
    long long E = in_sizes[9] / 2;
    float* out = (float*)d_out;

    int nScanBlocks = (N + 1023) / 1024;

    // Lazily-created side stream + events for a graph fork
    // (batch-dtype + counts + gemm1  ||  CSR build).
    static cudaStream_t s2 = nullptr;
    static cudaEvent_t evFork = nullptr, evJoin = nullptr;
    static int tried = 0;
    if (!tried) {
        tried = 1;
        if (cudaStreamCreateWithFlags(&s2, cudaStreamNonBlocking) != cudaSuccess) s2 = nullptr;
        if (s2) {
            if (cudaEventCreateWithFlags(&evFork, cudaEventDisableTiming) != cudaSuccess ||
                cudaEventCreateWithFlags(&evJoin, cudaEventDisableTiming) != cudaSuccess) {
                s2 = nullptr;
            }
        }
    }

    if (s2) {
        cudaEventRecord(evFork, 0);
        cudaStreamWaitEvent(s2, evFork, 0);
        detect_batch_kernel<<<1, 32, 0, s2>>>(bat, N);
        cnt_kernel<<<1, GMAX + 1, 0, s2>>>(bat, N);
        gemm1_kernel<<<(N + 63) / 64, 128, 0, s2>>>(X, W1, N);
        cudaEventRecord(evJoin, s2);
    }

    detect_kernel<<<1, 32>>>(ei, bat, E, N);
    init_kernel<<<(N + 255) / 256, 256>>>(N);
    hist_kernel<<<(int)((E + 255) / 256), 256>>>(ei, E);
    scan1_kernel<<<nScanBlocks, 1024>>>(N);
    scan2_kernel<<<1, 32>>>(nScanBlocks);
    scan3_kernel<<<(N + 255) / 256, 256>>>(N);
    fill_kernel<<<(int)((E + 255) / 256), 256>>>(ei, E);

    if (s2) {
        cudaStreamWaitEvent(0, evJoin, 0);
    } else {
        cnt_kernel<<<1, GMAX + 1>>>(bat, N);
        gemm1_kernel<<<(N + 63) / 64, 128>>>(X, W1, N);
    }

    scale_kernel<<<(N * 32 + 255) / 256, 256>>>(N);
    agg1_kernel<<<(N * 32 + 255) / 256, 256>>>(b1, bat, N);
    master1_kernel<<<GMAX, HDIM>>>(mW1, mb1);
    gemm2_kernel<<<(N + 127) / 128, 128>>>(bat, W2, N);
    agg2_kernel<<<(N * 32 + 255) / 256, 256>>>(b2, bat, N);
    master2_kernel<<<GMAX, KDIM>>>(mW2, mb2);
    softmax_kernel<<<(N * 32 + 255) / 256, 256>>>(bat, out, N);
}

// round 6
// speedup vs baseline: 1.6825x; 1.0085x over previous
#include <cuda_runtime.h>
#include <cuda_bf16.h>
#include <math.h>

#define NMAX  50176
#define EMAX  1664000
#define GMAX  64
#define FDIM  128
#define HDIM  128
#define KDIM  32

// ---------------- scratch (static device globals; no allocation) -------------
__device__ float g_dinv[NMAX];
__device__ float g_y1  [NMAX * HDIM];   // xw = X@W1 (UNSCALED fp32)
__device__ uint2 g_y1b [NMAX * 32];     // bf16(xw) UNSCALED: 4 bf16 per uint2
__device__ float g_h   [NMAX * HDIM];   // h after conv1 epilogue
__device__ float g_y2  [NMAX * KDIM];   // y2 = dinv*((h+r1)@W2)  (fp32)
__device__ unsigned short g_y2b[NMAX * KDIM];  // bf16 copy of y2
__device__ float g_z   [NMAX * KDIM];   // Z after conv2 epilogue
__device__ float g_msum1[GMAX * HDIM];
__device__ float g_r1  [GMAX * HDIM];
__device__ float g_msum2[GMAX * KDIM];
__device__ float g_r2  [GMAX * KDIM];
__device__ float g_cnt [GMAX];
__device__ int   g_cnt_i[NMAX];        // in-degree (without self loop)
__device__ int   g_rowstart[NMAX];
__device__ int   g_cursor[NMAX];
__device__ int   g_bsums[64];
__device__ int   g_csr  [EMAX];        // src ids sorted by dst
__device__ int   g_is64_ei;
__device__ int   g_is64_batch;

__device__ __forceinline__ long long ld_idx(const void* p, long long pos, int is64) {
    if (is64) return ((const long long*)p)[pos];
    return (long long)((const int*)p)[pos];
}

// ------------- dtype detection, parallelized across one warp -----------------
__global__ void detect_kernel(const void* ei, const void* batch, long long E, int N) {
    int lane = threadIdx.x;   // 32 threads, 2 samples each
    const unsigned long long* p = (const unsigned long long*)ei;
    bool ok = true;
#pragma unroll
    for (int u = 0; u < 2; u++) {
        int i = lane * 2 + u;
        long long w = (long long)i * (E - 1) / 63;
        if (p[w] >= (unsigned long long)N) ok = false;
    }
    unsigned all1 = __all_sync(0xffffffffu, ok);
    const unsigned long long* q = (const unsigned long long*)batch;
    bool ok2 = true;
#pragma unroll
    for (int u = 0; u < 2; u++) {
        int i = lane * 2 + u;
        long long w = (long long)(N / 2) - 1 - i;
        if (w >= 0 && q[w] >= (unsigned long long)GMAX) ok2 = false;
    }
    unsigned all2 = __all_sync(0xffffffffu, ok2);
    if (lane == 0) {
        g_is64_ei = (int)(all1 != 0);
        g_is64_batch = (int)(all2 != 0);
    }
}

// side-stream copy: batch dtype only (parallel)
__global__ void detect_batch_kernel(const void* batch, int N) {
    int lane = threadIdx.x;
    const unsigned long long* q = (const unsigned long long*)batch;
    bool ok2 = true;
#pragma unroll
    for (int u = 0; u < 2; u++) {
        int i = lane * 2 + u;
        long long w = (long long)(N / 2) - 1 - i;
        if (w >= 0 && q[w] >= (unsigned long long)GMAX) ok2 = false;
    }
    unsigned all2 = __all_sync(0xffffffffu, ok2);
    if (lane == 0) g_is64_batch = (int)(all2 != 0);
}

// ---------------- init: zero counters ----------------------------------------
__global__ void init_kernel(int N) {
    int idx = blockIdx.x * blockDim.x + threadIdx.x;
    if (idx < N)           g_cnt_i[idx] = 0;
    if (idx < GMAX * HDIM) g_msum1[idx] = 0.f;
    if (idx < GMAX * KDIM) g_msum2[idx] = 0.f;
}

// ------- per-graph node counts via binary search over sorted batch -----------
__global__ void cnt_kernel(const void* __restrict__ batch, int N) {
    int g = threadIdx.x;           // 0..64
    if (g > GMAX) return;
    __shared__ int start[GMAX + 1];
    int is64 = g_is64_batch;
    int lo = 0, hi = N;
    while (lo < hi) {
        int mid = (lo + hi) >> 1;
        int v = (int)ld_idx(batch, mid, is64);
        if (v < g) lo = mid + 1; else hi = mid;
    }
    start[g] = lo;
    __syncthreads();
    if (g < GMAX) g_cnt[g] = (float)(start[g + 1] - start[g]);
}

// ------------- degree histogram (reads only dst half of ei) ------------------
__global__ void hist_kernel(const void* __restrict__ ei, long long E) {
    long long e = (long long)blockIdx.x * blockDim.x + threadIdx.x;
    if (e >= E) return;
    int d = (int)ld_idx(ei, E + e, g_is64_ei);
    atomicAdd(&g_cnt_i[d], 1);
}

// ------------- prefix-sum over node counts (2 kernels) ------------------------
__global__ void scan1_kernel(int N) {
    __shared__ int sm[1024];
    int t = threadIdx.x;
    int idx = blockIdx.x * 1024 + t;
    int val = (idx < N) ? g_cnt_i[idx] : 0;
    sm[t] = val;
    __syncthreads();
    for (int off = 1; off < 1024; off <<= 1) {
        int x = (t >= off) ? sm[t - off] : 0;
        __syncthreads();
        sm[t] += x;
        __syncthreads();
    }
    if (idx < N) g_rowstart[idx] = sm[t] - val;   // exclusive, block-local
    if (t == 1023) g_bsums[blockIdx.x] = sm[1023];
}
// scan3 also performs the bsums prefix (64-wide shuffle scan) per block.
__global__ void scan3_kernel(int N, int nb) {
    __shared__ int pref[64];
    int t = threadIdx.x;
    if (t < 32) {
        int a = (t < nb) ? g_bsums[t] : 0;
        int b = (t + 32 < nb) ? g_bsums[t + 32] : 0;
        int sa = a, sb = b;
#pragma unroll
        for (int o = 1; o < 32; o <<= 1) {
            int va = __shfl_up_sync(0xffffffffu, sa, o);
            int vb = __shfl_up_sync(0xffffffffu, sb, o);
            if (t >= o) { sa += va; sb += vb; }
        }
        int totalA = __shfl_sync(0xffffffffu, sa, 31);
        pref[t]      = sa - a;           // exclusive
        pref[t + 32] = totalA + sb - b;  // exclusive
    }
    __syncthreads();
    int idx = blockIdx.x * blockDim.x + t;
    if (idx >= N) return;
    int v = g_rowstart[idx] + pref[idx >> 10];
    g_rowstart[idx] = v;
    g_cursor[idx]   = v;
    g_dinv[idx]     = rsqrtf((float)g_cnt_i[idx] + 1.0f);   // +1 self loop
}

// ------------- scatter-fill CSR directly from ei ------------------------------
__global__ void fill_kernel(const void* __restrict__ ei, long long E) {
    long long e = (long long)blockIdx.x * blockDim.x + threadIdx.x;
    if (e >= E) return;
    int is64 = g_is64_ei;
    int s = (int)ld_idx(ei, e, is64);
    int d = (int)ld_idx(ei, E + e, is64);
    int pos = atomicAdd(&g_cursor[d], 1);
    g_csr[pos] = s;
}

// ------- GEMM1: xw = X @ W1 (unscaled); dual fp32 + bf16 output --------------
__global__ void __launch_bounds__(128) gemm1_kernel(
    const float* __restrict__ X, const float* __restrict__ W, int N)
{
    __shared__ float As[16][64];
    __shared__ float Bs[16][128];
    int t  = threadIdx.x;
    int tx = t & 15;
    int ty = t >> 4;
    int rowBase = blockIdx.x * 64;

    float acc[8][8];
#pragma unroll
    for (int i = 0; i < 8; i++)
#pragma unroll
        for (int j = 0; j < 8; j++) acc[i][j] = 0.f;

    for (int k0 = 0; k0 < 128; k0 += 16) {
#pragma unroll
        for (int u = 0; u < 2; u++) {
            int idx = t * 8 + u * 4;
            int r = idx >> 4, c = idx & 15;
            int grow = rowBase + r;
            float4 v = make_float4(0.f, 0.f, 0.f, 0.f);
            if (grow < N) v = *(const float4*)(X + (size_t)grow * 128 + k0 + c);
            As[c + 0][r] = v.x; As[c + 1][r] = v.y;
            As[c + 2][r] = v.z; As[c + 3][r] = v.w;
        }
#pragma unroll
        for (int u = 0; u < 4; u++) {
            int idx = t * 16 + u * 4;
            int r = idx >> 7, c = idx & 127;
            *(float4*)&Bs[r][c] = *(const float4*)(W + (k0 + r) * 128 + c);
        }
        __syncthreads();
#pragma unroll
        for (int kk = 0; kk < 16; kk++) {
            float a[8], b[8];
            *(float4*)&a[0] = *(float4*)&As[kk][ty * 8];
            *(float4*)&a[4] = *(float4*)&As[kk][ty * 8 + 4];
            *(float4*)&b[0] = *(float4*)&Bs[kk][tx * 8];
            *(float4*)&b[4] = *(float4*)&Bs[kk][tx * 8 + 4];
#pragma unroll
            for (int i = 0; i < 8; i++)
#pragma unroll
                for (int j = 0; j < 8; j++)
                    acc[i][j] += a[i] * b[j];
        }
        __syncthreads();
    }
#pragma unroll
    for (int i = 0; i < 8; i++) {
        int grow = rowBase + ty * 8 + i;
        if (grow < N) {
#pragma unroll
            for (int j = 0; j < 8; j += 4) {
                float4 v;
                v.x = acc[i][j + 0]; v.y = acc[i][j + 1];
                v.z = acc[i][j + 2]; v.w = acc[i][j + 3];
                *(float4*)(g_y1 + (size_t)grow * 128 + tx * 8 + j) = v;
                __nv_bfloat162 lo = __floats2bfloat162_rn(v.x, v.y);
                __nv_bfloat162 hi = __floats2bfloat162_rn(v.z, v.w);
                uint2 o;
                o.x = *(unsigned*)&lo;
                o.y = *(unsigned*)&hi;
                g_y1b[(size_t)grow * 32 + tx * 2 + (j >> 2)] = o;
            }
        }
    }
}

// ---- agg1: h = elu(dinv[i]*(dinv[i]*xw[i] + sum dinv[s]*bf16(xw[s])) + b1) --
__global__ void __launch_bounds__(256) agg1_kernel(
    const float* __restrict__ b1, const void* __restrict__ batch, int N)
{
    int warp = (blockIdx.x * blockDim.x + threadIdx.x) >> 5;
    int lane = threadIdx.x & 31;
    if (warp >= N) return;
    int i = warp;
    int beg  = g_rowstart[i];
    int cntE = g_cnt_i[i];
    float dv = g_dinv[i];
    float4 self = ((const float4*)g_y1)[(size_t)i * 32 + lane];
    float4 acc;
    acc.x = dv * self.x; acc.y = dv * self.y;
    acc.z = dv * self.z; acc.w = dv * self.w;
    int full = cntE & ~31;
    for (int k = 0; k < full; k += 32) {
        int   myS = g_csr[beg + k + lane];
        float myD = g_dinv[myS];
#pragma unroll 8
        for (int j = 0; j < 32; j++) {
            int   s = __shfl_sync(0xffffffffu, myS, j);
            float w = __shfl_sync(0xffffffffu, myD, j);
            uint2 v = g_y1b[(size_t)s * 32 + lane];
            float2 a = __bfloat1622float2(*(__nv_bfloat162*)&v.x);
            float2 b = __bfloat1622float2(*(__nv_bfloat162*)&v.y);
            acc.x += w * a.x; acc.y += w * a.y;
            acc.z += w * b.x; acc.w += w * b.y;
        }
    }
    int rem = cntE - full;
    if (rem) {
        int   myS = (lane < rem) ? g_csr[beg + full + lane] : 0;
        float myD = (lane < rem) ? g_dinv[myS] : 0.f;
        for (int j = 0; j < rem; j++) {
            int   s = __shfl_sync(0xffffffffu, myS, j);
            float w = __shfl_sync(0xffffffffu, myD, j);
            uint2 v = g_y1b[(size_t)s * 32 + lane];
            float2 a = __bfloat1622float2(*(__nv_bfloat162*)&v.x);
            float2 b = __bfloat1622float2(*(__nv_bfloat162*)&v.y);
            acc.x += w * a.x; acc.y += w * a.y;
            acc.z += w * b.x; acc.w += w * b.y;
        }
    }
    float4 bb = ((const float4*)b1)[lane];
    float4 h;
    float vx = dv * acc.x + bb.x; h.x = vx > 0.f ? vx : expm1f(vx);
    float vy = dv * acc.y + bb.y; h.y = vy > 0.f ? vy : expm1f(vy);
    float vz = dv * acc.z + bb.z; h.z = vz > 0.f ? vz : expm1f(vz);
    float vw = dv * acc.w + bb.w; h.w = vw > 0.f ? vw : expm1f(vw);
    ((float4*)g_h)[(size_t)i * 32 + lane] = h;
    int g = (int)ld_idx(batch, i, g_is64_batch);
    float* ms = g_msum1 + g * HDIM + lane * 4;
    asm volatile("red.global.add.v4.f32 [%0], {%1, %2, %3, %4};"
                 :: "l"(ms), "f"(h.x), "f"(h.y), "f"(h.z), "f"(h.w) : "memory");
}

// ---------------- master1: r1 = relu(mean_pool(h) @ mW1 + mb1) ---------------
__global__ void master1_kernel(const float* __restrict__ mW1,
                               const float* __restrict__ mb1) {
    __shared__ float m[HDIM];
    int g = blockIdx.x, j = threadIdx.x;
    float c = fmaxf(g_cnt[g], 1.f);
    m[j] = g_msum1[g * HDIM + j] / c;
    __syncthreads();
    float a = mb1[j];
#pragma unroll 4
    for (int k = 0; k < HDIM; k++) a += m[k] * mW1[k * HDIM + j];
    g_r1[g * HDIM + j] = fmaxf(a, 0.f);
}

// ------- GEMM2: y2 = dinv.*((h + r1[batch]) @ W2); also bf16 copy y2b --------
__global__ void __launch_bounds__(128) gemm2_kernel(
    const void* __restrict__ batch, const float* __restrict__ W2, int N)
{
    __shared__ float Ws[128 * 32];
    int t = threadIdx.x;
#pragma unroll
    for (int u = 0; u < 8; u++) {
        int idx = u * 512 + t * 4;
        *(float4*)&Ws[idx] = *(const float4*)&W2[idx];
    }
    __syncthreads();
    int i = blockIdx.x * 128 + t;
    if (i >= N) return;
    int g = (int)ld_idx(batch, i, g_is64_batch);
    const float* hr = g_h + (size_t)i * 128;
    const float* rr = g_r1 + g * 128;
    float4 acc[8];
#pragma unroll
    for (int j = 0; j < 8; j++) acc[j] = make_float4(0.f, 0.f, 0.f, 0.f);
#pragma unroll 2
    for (int k0 = 0; k0 < 128; k0 += 4) {
        float4 xv = *(const float4*)(hr + k0);
        float4 rv = *(const float4*)(rr + k0);
        float xs[4] = {xv.x + rv.x, xv.y + rv.y, xv.z + rv.z, xv.w + rv.w};
#pragma unroll
        for (int kk = 0; kk < 4; kk++) {
            const float4* wrow = (const float4*)&Ws[(k0 + kk) * 32];
            float x = xs[kk];
#pragma unroll
            for (int j = 0; j < 8; j++) {
                float4 w = wrow[j];
                acc[j].x += x * w.x; acc[j].y += x * w.y;
                acc[j].z += x * w.z; acc[j].w += x * w.w;
            }
        }
    }
    float dv = g_dinv[i];
#pragma unroll
    for (int j = 0; j < 8; j++) {
        float4 v = acc[j];
        v.x *= dv; v.y *= dv; v.z *= dv; v.w *= dv;
        *(float4*)(g_y2 + (size_t)i * 32 + j * 4) = v;
        __nv_bfloat162 lo = __floats2bfloat162_rn(v.x, v.y);
        __nv_bfloat162 hi = __floats2bfloat162_rn(v.z, v.w);
        unsigned* dstb = (unsigned*)(g_y2b + (size_t)i * 32 + j * 4);
        dstb[0] = *(unsigned*)&lo;
        dstb[1] = *(unsigned*)&hi;
    }
}

// ----- agg2 (bf16 gather) + epilogue: Z = dinv*(self + sum) + b2; fused pool -
__global__ void __launch_bounds__(256) agg2_kernel(
    const float* __restrict__ b2, const void* __restrict__ batch, int N)
{
    int warp = (blockIdx.x * blockDim.x + threadIdx.x) >> 5;
    int lane = threadIdx.x & 31;
    if (warp >= N) return;
    int i = warp;
    int beg  = g_rowstart[i];
    int cntE = g_cnt_i[i];
    float acc = g_y2[(size_t)i * 32 + lane];    // self loop in fp32 (pre-scaled)
    int full = cntE & ~31;
    for (int k = 0; k < full; k += 32) {
        int myS = g_csr[beg + k + lane];
#pragma unroll 8
        for (int j = 0; j < 32; j++) {
            int s = __shfl_sync(0xffffffffu, myS, j);
            unsigned short raw = g_y2b[(size_t)s * 32 + lane];
            acc += __bfloat162float(*(__nv_bfloat16*)&raw);
        }
    }
    int rem = cntE - full;
    if (rem) {
        int myS = (lane < rem) ? g_csr[beg + full + lane] : 0;
        for (int j = 0; j < rem; j++) {
            int s = __shfl_sync(0xffffffffu, myS, j);
            unsigned short raw = g_y2b[(size_t)s * 32 + lane];
            acc += __bfloat162float(*(__nv_bfloat16*)&raw);
        }
    }
    float z = g_dinv[i] * acc + b2[lane];
    g_z[(size_t)i * 32 + lane] = z;
    int g = (int)ld_idx(batch, i, g_is64_batch);
    atomicAdd(&g_msum2[g * KDIM + lane], z);
}

// ---------------- master2: r2 = relu(mean_pool(Z) @ mW2 + mb2) ---------------
__global__ void master2_kernel(const float* __restrict__ mW2,
                               const float* __restrict__ mb2) {
    __shared__ float m[KDIM];
    int g = blockIdx.x, j = threadIdx.x;
    float c = fmaxf(g_cnt[g], 1.f);
    m[j] = g_msum2[g * KDIM + j] / c;
    __syncthreads();
    float a = mb2[j];
#pragma unroll
    for (int k = 0; k < KDIM; k++) a += m[k] * mW2[k * KDIM + j];
    g_r2[g * KDIM + j] = fmaxf(a, 0.f);
}

// ---------------- softmax over 32 cols (1 warp per row) ----------------------
__global__ void softmax_kernel(const void* __restrict__ batch,
                               float* __restrict__ out, int N) {
    int gtid = blockIdx.x * blockDim.x + threadIdx.x;
    int i = gtid >> 5;
    int j = threadIdx.x & 31;
    if (i >= N) return;
    int g = (int)ld_idx(batch, i, g_is64_batch);
    float z = g_z[(size_t)i * 32 + j] + g_r2[g * 32 + j];
    float m = z;
#pragma unroll
    for (int o = 16; o > 0; o >>= 1) m = fmaxf(m, __shfl_xor_sync(0xffffffffu, m, o));
    float e = __expf(z - m);
    float s = e;
#pragma unroll
    for (int o = 16; o > 0; o >>= 1) s += __shfl_xor_sync(0xffffffffu, s, o);
    out[(size_t)i * 32 + j] = e / s;
}

// ---------------- launch ------------------------------------------------------
extern "C" void kernel_launch(void* const* d_in, const int* in_sizes, int n_in,
                              void* d_out, int out_size) {
    const float* X   = (const float*)d_in[0];
    const float* W1  = (const float*)d_in[1];
    const float* b1  = (const float*)d_in[2];
    const float* W2  = (const float*)d_in[3];
    const float* b2  = (const float*)d_in[4];
    const float* mW1 = (const float*)d_in[5];
    const float* mb1 = (const float*)d_in[6];
    const float* mW2 = (const float*)d_in[7];
    const float* mb2 = (const float*)d_in[8];
    const void*  ei  = d_in[9];
    const void*  bat = d_in[10];

    int N = in_sizes[0] / FDIM;
    long long E = in_sizes[9] / 2;
    float* out = (float*)d_out;

    int nScanBlocks = (N + 1023) / 1024;

    // Side stream: gemm1 (then cnt) runs concurrently with the CSR build.
    static cudaStream_t s2 = nullptr;
    static cudaEvent_t evFork = nullptr, evJoin = nullptr, evJoin2 = nullptr;
    static int tried = 0;
    if (!tried) {
        tried = 1;
        if (cudaStreamCreateWithFlags(&s2, cudaStreamNonBlocking) != cudaSuccess) s2 = nullptr;
        if (s2) {
            if (cudaEventCreateWithFlags(&evFork, cudaEventDisableTiming) != cudaSuccess ||
                cudaEventCreateWithFlags(&evJoin, cudaEventDisableTiming) != cudaSuccess ||
                cudaEventCreateWithFlags(&evJoin2, cudaEventDisableTiming) != cudaSuccess) {
                s2 = nullptr;
            }
        }
    }

    if (s2) {
        cudaEventRecord(evFork, 0);
        cudaStreamWaitEvent(s2, evFork, 0);
        detect_batch_kernel<<<1, 32, 0, s2>>>(bat, N);
        gemm1_kernel<<<(N + 63) / 64, 128, 0, s2>>>(X, W1, N);
        cudaEventRecord(evJoin, s2);
        cnt_kernel<<<1, GMAX + 1, 0, s2>>>(bat, N);   // overlaps agg1 on main
        cudaEventRecord(evJoin2, s2);
    }

    detect_kernel<<<1, 32>>>(ei, bat, E, N);
    init_kernel<<<(N + 255) / 256, 256>>>(N);
    hist_kernel<<<(int)((E + 255) / 256), 256>>>(ei, E);
    scan1_kernel<<<nScanBlocks, 1024>>>(N);
    scan3_kernel<<<(N + 255) / 256, 256>>>(N, nScanBlocks);
    fill_kernel<<<(int)((E + 255) / 256), 256>>>(ei, E);

    if (s2) {
        cudaStreamWaitEvent(0, evJoin, 0);
    } else {
        gemm1_kernel<<<(N + 63) / 64, 128>>>(X, W1, N);
        cnt_kernel<<<1, GMAX + 1>>>(bat, N);
    }

    agg1_kernel<<<(N * 32 + 255) / 256, 256>>>(b1, bat, N);
    if (s2) cudaStreamWaitEvent(0, evJoin2, 0);
    master1_kernel<<<GMAX, HDIM>>>(mW1, mb1);
    gemm2_kernel<<<(N + 127) / 128, 128>>>(bat, W2, N);
    agg2_kernel<<<(N * 32 + 255) / 256, 256>>>(b2, bat, N);
    master2_kernel<<<GMAX, KDIM>>>(mW2, mb2);
    softmax_kernel<<<(N * 32 + 255) / 256, 256>>>(bat, out, N);
}